// round 1
// baseline (speedup 1.0000x reference)
#include <cuda_runtime.h>

// HeadProbEncoder: B=8, L=512, d=64, n_head=12, K=2 triangle groups, 4 iterations.
// Simplified exact recurrence (DAMPING=0, STEPSIZE=1, REG=1):
//   p   = softmax_d(q_z) * mask1d
//   A   = p @ (64*ternary)              [z,k,c,i,b]
//   S   = A_k(i,j) . p_j  (k by triangle; diag=0)
//   P   = softmax_j(S) with diag included in normalizer, then zeroed
//   W_k = sum_{j in tri_k} P * p_j      [z,k,c,i,b]
//   q_z = (x + sum_{k,c,b} W * T) / 64

#define BB 8
#define LL 512
#define DD 64
#define HH 12
#define KH 24                 // 2*HH
#define NROW (BB*LL)          // 4096
#define NELT (BB*LL*DD)       // 262144

// -------- scratch (static device globals; no allocation anywhere) --------
__device__ float g_P[NELT];                    // softmax probs [z][i][a]
__device__ float g_A[BB*KH*LL*DD];             // [z][k*H+c][i][b]   24 MB
__device__ float g_W[BB*KH*LL*DD];             // [z][k*H+c][i][b]   24 MB
__device__ float g_S[BB*HH*LL*LL];             // raw scores         96 MB
__device__ float g_stats[BB*HH*LL*2];          // per-row (max, sumexp)
__device__ float g_Tr[KH*DD*DD];               // T rearranged [kc][a][b]
__device__ float g_Trt[KH*DD*DD];              // T rearranged [kc][b][a]
__device__ float g_Gpart[6*NELT];              // split-kc partial G

#define FMA16(A_, fa_, fp_) do { \
  A_[0][0] += fa_.x*fp_.x; A_[0][1] += fa_.x*fp_.y; A_[0][2] += fa_.x*fp_.z; A_[0][3] += fa_.x*fp_.w; \
  A_[1][0] += fa_.y*fp_.x; A_[1][1] += fa_.y*fp_.y; A_[1][2] += fa_.y*fp_.z; A_[1][3] += fa_.y*fp_.w; \
  A_[2][0] += fa_.z*fp_.x; A_[2][1] += fa_.z*fp_.y; A_[2][2] += fa_.z*fp_.z; A_[2][3] += fa_.z*fp_.w; \
  A_[3][0] += fa_.w*fp_.x; A_[3][1] += fa_.w*fp_.y; A_[3][2] += fa_.w*fp_.z; A_[3][3] += fa_.w*fp_.w; \
} while (0)

// -------- K0: rearrange ternary (once) --------
__global__ void k_prep_T(const float* __restrict__ ternary) {
    int idx = blockIdx.x * blockDim.x + threadIdx.x;
    if (idx >= 2*DD*DD*HH) return;
    int c = idx % HH; int t = idx / HH;
    int b = t % DD;   t /= DD;
    int a = t % DD;   int k = t / DD;
    float v = 64.0f * ternary[idx];
    int kc = k*HH + c;
    g_Tr [(kc*DD + a)*DD + b] = v;
    g_Trt[(kc*DD + b)*DD + a] = v;
}

// -------- K1: p = softmax_d(q_z) * mask ; q_z = x or (x+SumG)/64 --------
__global__ void k_softmax_p(const float* __restrict__ x, const int* __restrict__ mask, int use_g) {
    int gw = (blockIdx.x * blockDim.x + threadIdx.x) >> 5;
    int lane = threadIdx.x & 31;
    if (gw >= NROW) return;
    int base = gw * DD;
    float v0 = x[base + lane], v1 = x[base + lane + 32];
    if (use_g) {
        #pragma unroll
        for (int g = 0; g < 6; g++) {
            v0 += g_Gpart[g*NELT + base + lane];
            v1 += g_Gpart[g*NELT + base + lane + 32];
        }
        v0 *= (1.0f/64.0f); v1 *= (1.0f/64.0f);
    }
    float m = fmaxf(v0, v1);
    #pragma unroll
    for (int off = 16; off; off >>= 1) m = fmaxf(m, __shfl_xor_sync(0xffffffffu, m, off));
    float e0 = __expf(v0 - m), e1 = __expf(v1 - m);
    float s = e0 + e1;
    #pragma unroll
    for (int off = 16; off; off >>= 1) s += __shfl_xor_sync(0xffffffffu, s, off);
    float mm = (mask[gw] != 0) ? 1.0f : 0.0f;
    float inv = mm / s;
    g_P[base + lane]      = e0 * inv;
    g_P[base + lane + 32] = e1 * inv;
}

// -------- K2: A[z][kc][i][b] = sum_a p[z,i,a] * Tr[kc][a][b] --------
__global__ void __launch_bounds__(256) k_computeA() {
    __shared__ float sPt[DD][68];   // [a][i]
    __shared__ float sT [DD][68];   // [a][b]
    int i0 = blockIdx.x * 64, kc = blockIdx.y, z = blockIdx.z;
    int tid = threadIdx.x;
    for (int t = tid; t < 1024; t += 256) {
        int i = t >> 4, a4 = (t & 15) << 2;
        float4 v = *(const float4*)&g_P[(z*LL + i0 + i)*DD + a4];
        sPt[a4][i] = v.x; sPt[a4+1][i] = v.y; sPt[a4+2][i] = v.z; sPt[a4+3][i] = v.w;
    }
    for (int t = tid; t < 1024; t += 256) {
        int a = t >> 4, b4 = (t & 15) << 2;
        *(float4*)&sT[a][b4] = *(const float4*)&g_Tr[(kc*DD + a)*DD + b4];
    }
    __syncthreads();
    int ty = tid >> 4, tx = tid & 15;
    float acc[4][4] = {};
    #pragma unroll 8
    for (int a = 0; a < DD; a++) {
        float4 fa = *(float4*)&sPt[a][ty*4];
        float4 fp = *(float4*)&sT[a][tx*4];
        FMA16(acc, fa, fp);
    }
    #pragma unroll
    for (int r = 0; r < 4; r++)
        *(float4*)&g_A[((z*KH + kc)*LL + i0 + ty*4 + r)*DD + tx*4] =
            make_float4(acc[r][0], acc[r][1], acc[r][2], acc[r][3]);
}

// -------- K3: scores S + online per-row softmax stats --------
__global__ void __launch_bounds__(256) k_scores() {
    extern __shared__ float sm[];
    float (*sA0)[68] = (float(*)[68])(sm);             // [b][i]  (k=0)
    float (*sA1)[68] = (float(*)[68])(sm + 64*68);     // [b][i]  (k=1)
    float (*sPt)[68] = (float(*)[68])(sm + 2*64*68);   // [b][j]
    int i0 = blockIdx.x * 64, c = blockIdx.y, z = blockIdx.z;
    int tid = threadIdx.x, ty = tid >> 4, tx = tid & 15;
    for (int t = tid; t < 1024; t += 256) {
        int i = t >> 4, b4 = (t & 15) << 2;
        float4 v0 = *(const float4*)&g_A[((z*KH + c)*LL + i0 + i)*DD + b4];
        sA0[b4][i]=v0.x; sA0[b4+1][i]=v0.y; sA0[b4+2][i]=v0.z; sA0[b4+3][i]=v0.w;
        float4 v1 = *(const float4*)&g_A[((z*KH + HH + c)*LL + i0 + i)*DD + b4];
        sA1[b4][i]=v1.x; sA1[b4+1][i]=v1.y; sA1[b4+2][i]=v1.z; sA1[b4+3][i]=v1.w;
    }
    float m[4], ss[4];
    #pragma unroll
    for (int r = 0; r < 4; r++) { m[r] = -1e30f; ss[r] = 0.0f; }

    for (int jt = 0; jt < 8; jt++) {
        int j0 = jt * 64;
        __syncthreads();
        for (int t = tid; t < 1024; t += 256) {
            int j = t >> 4, b4 = (t & 15) << 2;
            float4 v = *(const float4*)&g_P[(z*LL + j0 + j)*DD + b4];
            sPt[b4][j]=v.x; sPt[b4+1][j]=v.y; sPt[b4+2][j]=v.z; sPt[b4+3][j]=v.w;
        }
        __syncthreads();
        float vals[4][4];
        if (j0 != i0) {
            float (*As)[68] = (j0 > i0) ? sA0 : sA1;
            float acc[4][4] = {};
            #pragma unroll 8
            for (int b = 0; b < DD; b++) {
                float4 fa = *(float4*)&As[b][ty*4];
                float4 fp = *(float4*)&sPt[b][tx*4];
                FMA16(acc, fa, fp);
            }
            #pragma unroll
            for (int r = 0; r < 4; r++)
                #pragma unroll
                for (int s = 0; s < 4; s++) vals[r][s] = acc[r][s];
        } else {
            float a0[4][4] = {}, a1[4][4] = {};
            #pragma unroll 4
            for (int b = 0; b < DD; b++) {
                float4 f0 = *(float4*)&sA0[b][ty*4];
                float4 f1 = *(float4*)&sA1[b][ty*4];
                float4 fp = *(float4*)&sPt[b][tx*4];
                FMA16(a0, f0, fp);
                FMA16(a1, f1, fp);
            }
            #pragma unroll
            for (int r = 0; r < 4; r++) {
                int gi = i0 + ty*4 + r;
                #pragma unroll
                for (int s = 0; s < 4; s++) {
                    int gj = j0 + tx*4 + s;
                    vals[r][s] = (gj > gi) ? a0[r][s] : ((gj < gi) ? a1[r][s] : 0.0f);
                }
            }
        }
        #pragma unroll
        for (int r = 0; r < 4; r++) {
            int gi = i0 + ty*4 + r;
            *(float4*)&g_S[((z*HH + c)*LL + gi)*LL + j0 + tx*4] =
                make_float4(vals[r][0], vals[r][1], vals[r][2], vals[r][3]);
            float tm = fmaxf(fmaxf(vals[r][0], vals[r][1]), fmaxf(vals[r][2], vals[r][3]));
            float nm = fmaxf(m[r], tm);
            ss[r] = ss[r] * __expf(m[r] - nm)
                  + __expf(vals[r][0]-nm) + __expf(vals[r][1]-nm)
                  + __expf(vals[r][2]-nm) + __expf(vals[r][3]-nm);
            m[r] = nm;
        }
    }
    // reduce (m, s) across the 16 tx-lanes that share each row
    #pragma unroll
    for (int r = 0; r < 4; r++) {
        float mr = m[r], sr = ss[r];
        #pragma unroll
        for (int off = 1; off < 16; off <<= 1) {
            float om = __shfl_xor_sync(0xffffffffu, mr, off);
            float os = __shfl_xor_sync(0xffffffffu, sr, off);
            float nm = fmaxf(mr, om);
            sr = sr * __expf(mr - nm) + os * __expf(om - nm);
            mr = nm;
        }
        if (tx == 0) {
            int ridx = (z*HH + c)*LL + i0 + ty*4 + r;
            g_stats[ridx*2]     = mr;
            g_stats[ridx*2 + 1] = sr;
        }
    }
}

// -------- K5: normalize P on the fly, accumulate triangle-split W --------
__global__ void __launch_bounds__(256) k_probs_W() {
    __shared__ float sSt[64][68];   // [j][i] normalized probs
    __shared__ float sV [64][68];   // [j][b] p values
    __shared__ float sM[64], sIs[64];
    int i0 = blockIdx.x * 64, c = blockIdx.y, z = blockIdx.z;
    int tid = threadIdx.x, ty = tid >> 4, tx = tid & 15;
    if (tid < 64) {
        int ridx = (z*HH + c)*LL + i0 + tid;
        sM[tid]  = g_stats[ridx*2];
        sIs[tid] = 1.0f / g_stats[ridx*2 + 1];
    }
    float aU[4][4] = {}, aL[4][4] = {};
    for (int jt = 0; jt < 8; jt++) {
        int j0 = jt * 64;
        __syncthreads();
        for (int t = tid; t < 1024; t += 256) {
            int j = t >> 4, b4 = (t & 15) << 2;
            *(float4*)&sV[j][b4] = *(const float4*)&g_P[(z*LL + j0 + j)*DD + b4];
        }
        for (int t = tid; t < 1024; t += 256) {
            int i = t >> 4, j4 = (t & 15) << 2;
            float4 v = *(const float4*)&g_S[((z*HH + c)*LL + i0 + i)*LL + j0 + j4];
            float mi = sM[i], isi = sIs[i];
            sSt[j4  ][i] = __expf(v.x - mi) * isi;
            sSt[j4+1][i] = __expf(v.y - mi) * isi;
            sSt[j4+2][i] = __expf(v.z - mi) * isi;
            sSt[j4+3][i] = __expf(v.w - mi) * isi;
        }
        __syncthreads();
        if (j0 > i0) {
            #pragma unroll 8
            for (int j = 0; j < 64; j++) {
                float4 fP = *(float4*)&sSt[j][ty*4];
                float4 fV = *(float4*)&sV[j][tx*4];
                FMA16(aU, fP, fV);
            }
        } else if (j0 < i0) {
            #pragma unroll 8
            for (int j = 0; j < 64; j++) {
                float4 fP = *(float4*)&sSt[j][ty*4];
                float4 fV = *(float4*)&sV[j][tx*4];
                FMA16(aL, fP, fV);
            }
        } else {  // diagonal tile: per-element routing, j==i excluded (diag removal)
            #pragma unroll 4
            for (int j = 0; j < 64; j++) {
                float4 fP = *(float4*)&sSt[j][ty*4];
                float4 fV = *(float4*)&sV[j][tx*4];
                int gj = j0 + j, gi0 = i0 + ty*4;
                float4 fU, fL;
                fU.x = (gj > gi0  ) ? fP.x : 0.0f;  fL.x = (gj < gi0  ) ? fP.x : 0.0f;
                fU.y = (gj > gi0+1) ? fP.y : 0.0f;  fL.y = (gj < gi0+1) ? fP.y : 0.0f;
                fU.z = (gj > gi0+2) ? fP.z : 0.0f;  fL.z = (gj < gi0+2) ? fP.z : 0.0f;
                fU.w = (gj > gi0+3) ? fP.w : 0.0f;  fL.w = (gj < gi0+3) ? fP.w : 0.0f;
                FMA16(aU, fU, fV);
                FMA16(aL, fL, fV);
            }
        }
    }
    #pragma unroll
    for (int r = 0; r < 4; r++) {
        int i = i0 + ty*4 + r;
        *(float4*)&g_W[((z*KH + c     )*LL + i)*DD + tx*4] =
            make_float4(aU[r][0], aU[r][1], aU[r][2], aU[r][3]);
        *(float4*)&g_W[((z*KH + HH + c)*LL + i)*DD + tx*4] =
            make_float4(aL[r][0], aL[r][1], aL[r][2], aL[r][3]);
    }
}

// -------- K6: partial G over kc-groups: Gpart[grp] = sum_{kc in grp} W @ Trt --------
__global__ void __launch_bounds__(256) k_G() {
    __shared__ float sWt[64][68];   // [b][i]
    __shared__ float sT [64][68];   // [b][a]
    int i0 = blockIdx.x * 64, grp = blockIdx.y, z = blockIdx.z;
    int tid = threadIdx.x, ty = tid >> 4, tx = tid & 15;
    float acc[4][4] = {};
    for (int g = 0; g < 4; g++) {
        int kc = grp*4 + g;
        __syncthreads();
        for (int t = tid; t < 1024; t += 256) {
            int i = t >> 4, b4 = (t & 15) << 2;
            float4 v = *(const float4*)&g_W[((z*KH + kc)*LL + i0 + i)*DD + b4];
            sWt[b4][i]=v.x; sWt[b4+1][i]=v.y; sWt[b4+2][i]=v.z; sWt[b4+3][i]=v.w;
        }
        for (int t = tid; t < 1024; t += 256) {
            int b = t >> 4, a4 = (t & 15) << 2;
            *(float4*)&sT[b][a4] = *(const float4*)&g_Trt[(kc*DD + b)*DD + a4];
        }
        __syncthreads();
        #pragma unroll 8
        for (int b = 0; b < 64; b++) {
            float4 fW = *(float4*)&sWt[b][ty*4];
            float4 fT = *(float4*)&sT[b][tx*4];
            FMA16(acc, fW, fT);
        }
    }
    #pragma unroll
    for (int r = 0; r < 4; r++)
        *(float4*)&g_Gpart[(grp*NROW + z*LL + i0 + ty*4 + r)*DD + tx*4] =
            make_float4(acc[r][0], acc[r][1], acc[r][2], acc[r][3]);
}

// -------- K7: final output q_z = (x + sum_grp Gpart) / 64 --------
__global__ void k_final(const float* __restrict__ x, float* __restrict__ out) {
    int idx = blockIdx.x * blockDim.x + threadIdx.x;
    if (idx >= NELT) return;
    float v = x[idx];
    #pragma unroll
    for (int g = 0; g < 6; g++) v += g_Gpart[g*NELT + idx];
    out[idx] = v * (1.0f/64.0f);
}

extern "C" void kernel_launch(void* const* d_in, const int* in_sizes, int n_in,
                              void* d_out, int out_size) {
    const float* x       = (const float*)d_in[0];
    const int*   mask    = (const int*)d_in[1];
    const float* ternary = (const float*)d_in[2];
    for (int i = 0; i < n_in; i++) {           // robust to metadata ordering
        if      (in_sizes[i] == NELT)        x       = (const float*)d_in[i];
        else if (in_sizes[i] == BB*LL)       mask    = (const int*)d_in[i];
        else if (in_sizes[i] == 2*DD*DD*HH)  ternary = (const float*)d_in[i];
    }
    cudaFuncSetAttribute(k_scores, cudaFuncAttributeMaxDynamicSharedMemorySize, 3*64*68*4);

    k_prep_T<<<96, 1024>>>(ternary);
    for (int it = 0; it < 4; it++) {
        k_softmax_p<<<NROW/4, 128>>>(x, mask, it > 0 ? 1 : 0);
        k_computeA<<<dim3(8, KH, BB), 256>>>();
        k_scores  <<<dim3(8, HH, BB), 256, 3*64*68*4>>>();
        k_probs_W <<<dim3(8, HH, BB), 256>>>();
        k_G       <<<dim3(8, 6,  BB), 256>>>();
    }
    k_final<<<(NELT + 255)/256, 256>>>(x, (float*)d_out);
}

// round 2
// speedup vs baseline: 1.1576x; 1.1576x over previous
#include <cuda_runtime.h>

// HeadProbEncoder: B=8, L=512, d=64, n_head=12, K=2 triangles, 4 iterations.
// p = softmax_d(q_z)*mask; A = p@(64T); S = A.p^T (triangle-routed, diag=0);
// P = softmax_j(S) (diag in normalizer, then excluded); W_k = P_tri @ p;
// q_z = (x + sum W.T)/64.
// This round: f32x2 packed FMA, 8x4 fragments, transpose-free layouts.

#define BB 8
#define LL 512
#define DD 64
#define HH 12
#define KH 24
#define NROW (BB*LL)
#define NELT (BB*LL*DD)
#define SP 72                    // padded smem row stride (floats), 16B-aligned

typedef unsigned long long u64;

// -------- scratch (static device globals; no allocation anywhere) --------
__device__ float g_P [NELT];          // [z][i][b]
__device__ float g_Pt[BB*DD*LL];      // [z][b][i]
__device__ float g_A [BB*KH*DD*LL];   // [z][kc][b][i]
__device__ float g_W [BB*KH*DD*LL];   // [z][kc][b][i]
__device__ float g_S [BB*HH*LL*LL];   // [z][c][i][j]
__device__ float g_stats[BB*HH*LL*2];
__device__ float g_Tr [KH*DD*DD];     // [kc][a][b]
__device__ float g_Trt[KH*DD*DD];     // [kc][b][a]
__device__ float g_Gpart[6*NELT];

__device__ __forceinline__ u64 bc2(float v){ u64 r; asm("mov.b64 %0,{%1,%1};":"=l"(r):"f"(v)); return r; }
__device__ __forceinline__ void f2(u64 &d, u64 a, u64 b){ asm("fma.rn.f32x2 %0,%1,%2,%0;":"+l"(d):"l"(a),"l"(b)); }
__device__ __forceinline__ float2 up2(u64 v){ float2 f; asm("mov.b64 {%0,%1},%2;":"=f"(f.x),"=f"(f.y):"l"(v)); return f; }

#define STEP4(ACC,P0,P1,P2,P3,B0,B1,B2,B3) do{ \
  f2(ACC[0][0],P0,B0); f2(ACC[0][1],P0,B1); f2(ACC[0][2],P0,B2); f2(ACC[0][3],P0,B3); \
  f2(ACC[1][0],P1,B0); f2(ACC[1][1],P1,B1); f2(ACC[1][2],P1,B2); f2(ACC[1][3],P1,B3); \
  f2(ACC[2][0],P2,B0); f2(ACC[2][1],P2,B1); f2(ACC[2][2],P2,B2); f2(ACC[2][3],P2,B3); \
  f2(ACC[3][0],P3,B0); f2(ACC[3][1],P3,B1); f2(ACC[3][2],P3,B2); f2(ACC[3][3],P3,B3); \
} while(0)

// -------- K0: rearrange ternary --------
__global__ void k_prep_T(const float* __restrict__ ternary) {
    int idx = blockIdx.x * blockDim.x + threadIdx.x;
    if (idx >= 2*DD*DD*HH) return;
    int c = idx % HH; int t = idx / HH;
    int b = t % DD;   t /= DD;
    int a = t % DD;   int k = t / DD;
    float v = 64.0f * ternary[idx];
    int kc = k*HH + c;
    g_Tr [(kc*DD + a)*DD + b] = v;
    g_Trt[(kc*DD + b)*DD + a] = v;
}

// -------- K1: p = softmax_d(q_z)*mask; writes both P and P^T --------
__global__ void k_softmax_p(const float* __restrict__ x, const int* __restrict__ mask, int use_g) {
    int gw = (blockIdx.x * blockDim.x + threadIdx.x) >> 5;
    int lane = threadIdx.x & 31;
    if (gw >= NROW) return;
    int base = gw * DD;
    float v0 = x[base + lane], v1 = x[base + lane + 32];
    if (use_g) {
        #pragma unroll
        for (int g = 0; g < 6; g++) {
            v0 += g_Gpart[g*NELT + base + lane];
            v1 += g_Gpart[g*NELT + base + lane + 32];
        }
        v0 *= (1.0f/64.0f); v1 *= (1.0f/64.0f);
    }
    float m = fmaxf(v0, v1);
    #pragma unroll
    for (int off = 16; off; off >>= 1) m = fmaxf(m, __shfl_xor_sync(0xffffffffu, m, off));
    float e0 = __expf(v0 - m), e1 = __expf(v1 - m);
    float s = e0 + e1;
    #pragma unroll
    for (int off = 16; off; off >>= 1) s += __shfl_xor_sync(0xffffffffu, s, off);
    float mm = (mask[gw] != 0) ? 1.0f : 0.0f;
    float inv = mm / s;
    float p0 = e0 * inv, p1 = e1 * inv;
    g_P[base + lane]      = p0;
    g_P[base + lane + 32] = p1;
    int z = gw >> 9, i = gw & 511;
    g_Pt[(z*DD + lane     )*LL + i] = p0;
    g_Pt[(z*DD + lane + 32)*LL + i] = p1;
}

// -------- K2: A[b][i] = sum_a Pt[a][i] * Tr[a][b] --------
__global__ void __launch_bounds__(128) k_computeA() {
    __shared__ float sPt[DD*SP];   // [a][i]
    __shared__ float sT [DD*SP];   // [a][b]
    int i0 = blockIdx.x*64, kc = blockIdx.y, z = blockIdx.z;
    int tid = threadIdx.x, tx = tid & 15, ty = tid >> 4;
    for (int t = tid; t < 1024; t += 128) {
        int r = t >> 4, q = (t & 15) << 2;
        *(float4*)&sPt[r*SP+q] = *(const float4*)&g_Pt[(z*DD + r)*LL + i0 + q];
        *(float4*)&sT [r*SP+q] = *(const float4*)&g_Tr[(kc*DD + r)*DD + q];
    }
    __syncthreads();
    u64 acc[4][4] = {};
    #pragma unroll 8
    for (int a = 0; a < 64; a++) {
        ulonglong2 p01 = *(const ulonglong2*)&sPt[a*SP + ty*8];
        ulonglong2 p23 = *(const ulonglong2*)&sPt[a*SP + ty*8 + 4];
        float4 fp = *(const float4*)&sT[a*SP + tx*4];
        u64 b0=bc2(fp.x), b1=bc2(fp.y), b2=bc2(fp.z), b3=bc2(fp.w);
        STEP4(acc, p01.x, p01.y, p23.x, p23.y, b0, b1, b2, b3);
    }
    #pragma unroll
    for (int s = 0; s < 4; s++) {
        float* dst = &g_A[((z*KH + kc)*DD + tx*4 + s)*LL + i0 + ty*8];
        ((ulonglong2*)dst)[0] = make_ulonglong2(acc[0][s], acc[1][s]);
        ((ulonglong2*)dst)[1] = make_ulonglong2(acc[2][s], acc[3][s]);
    }
}

// -------- K3: S[i][j] + online row softmax stats --------
extern __shared__ float smem_dyn[];
__global__ void __launch_bounds__(128) k_scores() {
    float* sA0 = smem_dyn;             // [b][i] upper-triangle A
    float* sA1 = smem_dyn + 64*SP;     // [b][i] lower-triangle A
    float* sPj = smem_dyn + 2*64*SP;   // [b][j]
    int i0 = blockIdx.x*64, c = blockIdx.y, z = blockIdx.z;
    int tid = threadIdx.x, tx = tid & 15, ty = tid >> 4;
    for (int t = tid; t < 1024; t += 128) {
        int b = t >> 4, q = (t & 15) << 2;
        *(float4*)&sA0[b*SP+q] = *(const float4*)&g_A[((z*KH + c     )*DD + b)*LL + i0 + q];
        *(float4*)&sA1[b*SP+q] = *(const float4*)&g_A[((z*KH + HH + c)*DD + b)*LL + i0 + q];
    }
    float m[8], ss[8];
    #pragma unroll
    for (int r = 0; r < 8; r++) { m[r] = -1e30f; ss[r] = 0.0f; }

    for (int jt = 0; jt < 8; jt++) {
        int j0 = jt * 64;
        __syncthreads();
        for (int t = tid; t < 1024; t += 128) {
            int b = t >> 4, q = (t & 15) << 2;
            *(float4*)&sPj[b*SP+q] = *(const float4*)&g_Pt[(z*DD + b)*LL + j0 + q];
        }
        __syncthreads();
        float v[8][4];
        if (j0 != i0) {
            const float* sA = (j0 > i0) ? sA0 : sA1;
            u64 acc[4][4] = {};
            #pragma unroll 8
            for (int b = 0; b < 64; b++) {
                ulonglong2 a01 = *(const ulonglong2*)&sA[b*SP + ty*8];
                ulonglong2 a23 = *(const ulonglong2*)&sA[b*SP + ty*8 + 4];
                float4 fp = *(const float4*)&sPj[b*SP + tx*4];
                u64 b0=bc2(fp.x), b1=bc2(fp.y), b2=bc2(fp.z), b3=bc2(fp.w);
                STEP4(acc, a01.x, a01.y, a23.x, a23.y, b0, b1, b2, b3);
            }
            #pragma unroll
            for (int rp = 0; rp < 4; rp++)
                #pragma unroll
                for (int s = 0; s < 4; s++) {
                    float2 f = up2(acc[rp][s]);
                    v[2*rp][s] = f.x; v[2*rp+1][s] = f.y;
                }
        } else {
            u64 A0[4][4] = {}, A1[4][4] = {};
            #pragma unroll 4
            for (int b = 0; b < 64; b++) {
                ulonglong2 a01 = *(const ulonglong2*)&sA0[b*SP + ty*8];
                ulonglong2 a23 = *(const ulonglong2*)&sA0[b*SP + ty*8 + 4];
                ulonglong2 c01 = *(const ulonglong2*)&sA1[b*SP + ty*8];
                ulonglong2 c23 = *(const ulonglong2*)&sA1[b*SP + ty*8 + 4];
                float4 fp = *(const float4*)&sPj[b*SP + tx*4];
                u64 b0=bc2(fp.x), b1=bc2(fp.y), b2=bc2(fp.z), b3=bc2(fp.w);
                STEP4(A0, a01.x, a01.y, a23.x, a23.y, b0, b1, b2, b3);
                STEP4(A1, c01.x, c01.y, c23.x, c23.y, b0, b1, b2, b3);
            }
            #pragma unroll
            for (int rp = 0; rp < 4; rp++)
                #pragma unroll
                for (int s = 0; s < 4; s++) {
                    float2 f0 = up2(A0[rp][s]), f1 = up2(A1[rp][s]);
                    int gj = tx*4 + s;
                    int giA = ty*8 + 2*rp, giB = giA + 1;
                    v[2*rp  ][s] = (gj > giA) ? f0.x : ((gj < giA) ? f1.x : 0.0f);
                    v[2*rp+1][s] = (gj > giB) ? f0.y : ((gj < giB) ? f1.y : 0.0f);
                }
        }
        #pragma unroll
        for (int r = 0; r < 8; r++) {
            int gi = i0 + ty*8 + r;
            *(float4*)&g_S[((z*HH + c)*LL + gi)*LL + j0 + tx*4] =
                make_float4(v[r][0], v[r][1], v[r][2], v[r][3]);
            float tm = fmaxf(fmaxf(v[r][0], v[r][1]), fmaxf(v[r][2], v[r][3]));
            float nm = fmaxf(m[r], tm);
            ss[r] = ss[r] * __expf(m[r] - nm)
                  + __expf(v[r][0]-nm) + __expf(v[r][1]-nm)
                  + __expf(v[r][2]-nm) + __expf(v[r][3]-nm);
            m[r] = nm;
        }
    }
    #pragma unroll
    for (int r = 0; r < 8; r++) {
        float mr = m[r], sr = ss[r];
        #pragma unroll
        for (int off = 1; off < 16; off <<= 1) {
            float om = __shfl_xor_sync(0xffffffffu, mr, off);
            float os = __shfl_xor_sync(0xffffffffu, sr, off);
            float nm = fmaxf(mr, om);
            sr = sr * __expf(mr - nm) + os * __expf(om - nm);
            mr = nm;
        }
        if (tx == 0) {
            int ridx = (z*HH + c)*LL + i0 + ty*8 + r;
            g_stats[ridx*2]     = mr;
            g_stats[ridx*2 + 1] = sr;
        }
    }
}

// -------- K5: normalize on the fly, triangle-split W (diag excluded) --------
__global__ void __launch_bounds__(128) k_probs_W() {
    __shared__ float sSt[64*SP];   // [j][i ^ swz(j)]  normalized probs
    __shared__ float sV [64*SP];   // [j][b]
    __shared__ float sM[64], sIs[64];
    int i0 = blockIdx.x*64, c = blockIdx.y, z = blockIdx.z;
    int tid = threadIdx.x, tx = tid & 15, ty = tid >> 4;
    if (tid < 64) {
        int ridx = (z*HH + c)*LL + i0 + tid;
        sM[tid]  = g_stats[ridx*2];
        sIs[tid] = 1.0f / g_stats[ridx*2 + 1];
    }
    u64 aU[4][4] = {}, aL[4][4] = {};
    for (int jt = 0; jt < 8; jt++) {
        int j0 = jt * 64;
        __syncthreads();
        for (int t = tid; t < 1024; t += 128) {
            int j = t >> 4, q = (t & 15) << 2;
            *(float4*)&sV[j*SP+q] = *(const float4*)&g_P[(z*LL + j0 + j)*DD + q];
        }
        for (int t = tid; t < 1024; t += 128) {
            int i  = (t & 7) | (((t >> 5) & 7) << 3);
            int j4 = ((t >> 3) & 3) | (((t >> 8) & 3) << 2);
            float4 s4 = *(const float4*)&g_S[((z*HH + c)*LL + i0 + i)*LL + j0 + j4*4];
            float mi = sM[i], isi = sIs[i];
            int ic = i ^ ((j4 & 3) << 3);        // conflict-free XOR swizzle
            sSt[(j4*4+0)*SP + ic] = __expf(s4.x - mi) * isi;
            sSt[(j4*4+1)*SP + ic] = __expf(s4.y - mi) * isi;
            sSt[(j4*4+2)*SP + ic] = __expf(s4.z - mi) * isi;
            sSt[(j4*4+3)*SP + ic] = __expf(s4.w - mi) * isi;
        }
        __syncthreads();
        if (j0 != i0) {
            u64 (*A)[4] = (j0 > i0) ? aU : aL;
            #pragma unroll 8
            for (int j = 0; j < 64; j++) {
                int base = (ty*8) ^ (((j >> 2) & 3) << 3);
                ulonglong2 p01 = *(const ulonglong2*)&sSt[j*SP + base];
                ulonglong2 p23 = *(const ulonglong2*)&sSt[j*SP + base + 4];
                float4 fv = *(const float4*)&sV[j*SP + tx*4];
                u64 b0=bc2(fv.x), b1=bc2(fv.y), b2=bc2(fv.z), b3=bc2(fv.w);
                STEP4(A, p01.x, p01.y, p23.x, p23.y, b0, b1, b2, b3);
            }
        } else {
            #pragma unroll 4
            for (int j = 0; j < 64; j++) {
                int base = (ty*8) ^ (((j >> 2) & 3) << 3);
                ulonglong2 p01 = *(const ulonglong2*)&sSt[j*SP + base];
                ulonglong2 p23 = *(const ulonglong2*)&sSt[j*SP + base + 4];
                float4 fv = *(const float4*)&sV[j*SP + tx*4];
                u64 b0=bc2(fv.x), b1=bc2(fv.y), b2=bc2(fv.z), b3=bc2(fv.w);
                u64 pa[4] = {p01.x, p01.y, p23.x, p23.y};
                #pragma unroll
                for (int rp = 0; rp < 4; rp++) {
                    int il = ty*8 + rp*2;
                    u64 f = pa[rp];
                    u64 fL = (j < il)   ? f : ((j == il)   ? (f & 0xFFFFFFFF00000000ULL) : 0ULL);
                    u64 fU = (j > il+1) ? f : ((j == il+1) ? (f & 0x00000000FFFFFFFFULL) : 0ULL);
                    f2(aL[rp][0], fL, b0); f2(aL[rp][1], fL, b1); f2(aL[rp][2], fL, b2); f2(aL[rp][3], fL, b3);
                    f2(aU[rp][0], fU, b0); f2(aU[rp][1], fU, b1); f2(aU[rp][2], fU, b2); f2(aU[rp][3], fU, b3);
                }
            }
        }
    }
    #pragma unroll
    for (int s = 0; s < 4; s++) {
        float* dU = &g_W[((z*KH + c     )*DD + tx*4 + s)*LL + i0 + ty*8];
        ((ulonglong2*)dU)[0] = make_ulonglong2(aU[0][s], aU[1][s]);
        ((ulonglong2*)dU)[1] = make_ulonglong2(aU[2][s], aU[3][s]);
        float* dL = &g_W[((z*KH + HH + c)*DD + tx*4 + s)*LL + i0 + ty*8];
        ((ulonglong2*)dL)[0] = make_ulonglong2(aL[0][s], aL[1][s]);
        ((ulonglong2*)dL)[1] = make_ulonglong2(aL[2][s], aL[3][s]);
    }
}

// -------- K6: Gpart[grp] = sum_{kc in grp} W[b][i] @ Trt[b][a] --------
__global__ void __launch_bounds__(128) k_G() {
    __shared__ float sW[64*SP];   // [b][i]
    __shared__ float sT[64*SP];   // [b][a]
    int i0 = blockIdx.x*64, grp = blockIdx.y, z = blockIdx.z;
    int tid = threadIdx.x, tx = tid & 15, ty = tid >> 4;
    u64 acc[4][4] = {};
    for (int g = 0; g < 4; g++) {
        int kc = grp*4 + g;
        __syncthreads();
        for (int t = tid; t < 1024; t += 128) {
            int b = t >> 4, q = (t & 15) << 2;
            *(float4*)&sW[b*SP+q] = *(const float4*)&g_W[((z*KH + kc)*DD + b)*LL + i0 + q];
            *(float4*)&sT[b*SP+q] = *(const float4*)&g_Trt[(kc*DD + b)*DD + q];
        }
        __syncthreads();
        #pragma unroll 8
        for (int b = 0; b < 64; b++) {
            ulonglong2 w01 = *(const ulonglong2*)&sW[b*SP + ty*8];
            ulonglong2 w23 = *(const ulonglong2*)&sW[b*SP + ty*8 + 4];
            float4 ft = *(const float4*)&sT[b*SP + tx*4];
            u64 b0=bc2(ft.x), b1=bc2(ft.y), b2=bc2(ft.z), b3=bc2(ft.w);
            STEP4(acc, w01.x, w01.y, w23.x, w23.y, b0, b1, b2, b3);
        }
    }
    #pragma unroll
    for (int rp = 0; rp < 4; rp++) {
        float2 x0 = up2(acc[rp][0]), x1 = up2(acc[rp][1]);
        float2 x2 = up2(acc[rp][2]), x3 = up2(acc[rp][3]);
        int i = i0 + ty*8 + rp*2;
        *(float4*)&g_Gpart[(grp*NROW + z*LL + i    )*DD + tx*4] = make_float4(x0.x, x1.x, x2.x, x3.x);
        *(float4*)&g_Gpart[(grp*NROW + z*LL + i + 1)*DD + tx*4] = make_float4(x0.y, x1.y, x2.y, x3.y);
    }
}

// -------- K7: out = (x + sum Gpart) / 64 --------
__global__ void k_final(const float* __restrict__ x, float* __restrict__ out) {
    int idx = blockIdx.x * blockDim.x + threadIdx.x;
    if (idx >= NELT) return;
    float v = x[idx];
    #pragma unroll
    for (int g = 0; g < 6; g++) v += g_Gpart[g*NELT + idx];
    out[idx] = v * (1.0f/64.0f);
}

extern "C" void kernel_launch(void* const* d_in, const int* in_sizes, int n_in,
                              void* d_out, int out_size) {
    const float* x       = (const float*)d_in[0];
    const int*   mask    = (const int*)d_in[1];
    const float* ternary = (const float*)d_in[2];
    for (int i = 0; i < n_in; i++) {
        if      (in_sizes[i] == NELT)        x       = (const float*)d_in[i];
        else if (in_sizes[i] == BB*LL)       mask    = (const int*)d_in[i];
        else if (in_sizes[i] == 2*DD*DD*HH)  ternary = (const float*)d_in[i];
    }
    const int SCORES_SMEM = 3*64*SP*4;  // 55296 B
    cudaFuncSetAttribute(k_scores, cudaFuncAttributeMaxDynamicSharedMemorySize, SCORES_SMEM);

    k_prep_T<<<96, 1024>>>(ternary);
    for (int it = 0; it < 4; it++) {
        k_softmax_p<<<NROW/4, 128>>>(x, mask, it > 0 ? 1 : 0);
        k_computeA<<<dim3(8, KH, BB), 128>>>();
        k_scores  <<<dim3(8, HH, BB), 128, SCORES_SMEM>>>();
        k_probs_W <<<dim3(8, HH, BB), 128>>>();
        k_G       <<<dim3(8, 6,  BB), 128>>>();
    }
    k_final<<<(NELT + 255)/256, 256>>>(x, (float*)d_out);
}

// round 3
// speedup vs baseline: 1.2235x; 1.0570x over previous
#include <cuda_runtime.h>

// HeadProbEncoder: B=8, L=512, d=64, n_head=12, K=2 triangles, 4 iterations.
// Round 3: fused A+scores and W+G kernels, cp.async double-buffered tiles.

#define BB 8
#define LL 512
#define DD 64
#define HH 12
#define KH 24
#define NROW (BB*LL)
#define NELT (BB*LL*DD)
#define SP 72

typedef unsigned long long u64;

// -------- scratch --------
__device__ float g_P [NELT];          // [z][i][b]
__device__ float g_Pt[BB*DD*LL];      // [z][b][i]
__device__ float g_S [BB*HH*LL*LL];   // [z][c][i][j]
__device__ float g_stats[BB*HH*LL*2];
__device__ float g_Tr [KH*DD*DD];     // [kc][a][b]
__device__ float g_Trt[KH*DD*DD];     // [kc][b][a]
__device__ float g_Gpart[12*NELT];    // per-c G partials

__device__ __forceinline__ u64 bc2(float v){ u64 r; asm("mov.b64 %0,{%1,%1};":"=l"(r):"f"(v)); return r; }
__device__ __forceinline__ void f2(u64 &d, u64 a, u64 b){ asm("fma.rn.f32x2 %0,%1,%2,%0;":"+l"(d):"l"(a),"l"(b)); }
__device__ __forceinline__ float2 up2(u64 v){ float2 f; asm("mov.b64 {%0,%1},%2;":"=f"(f.x),"=f"(f.y):"l"(v)); return f; }
__device__ __forceinline__ unsigned smaddr(const void* p){ return (unsigned)__cvta_generic_to_shared(p); }
__device__ __forceinline__ void cpa16(unsigned s, const void* g){ asm volatile("cp.async.cg.shared.global [%0],[%1],16;"::"r"(s),"l"(g):"memory"); }
__device__ __forceinline__ void cpcommit(){ asm volatile("cp.async.commit_group;":::"memory"); }
__device__ __forceinline__ void cpwait0(){ asm volatile("cp.async.wait_group 0;":::"memory"); }

#define STEP4(ACC,P0,P1,P2,P3,B0,B1,B2,B3) do{ \
  f2(ACC[0][0],P0,B0); f2(ACC[0][1],P0,B1); f2(ACC[0][2],P0,B2); f2(ACC[0][3],P0,B3); \
  f2(ACC[1][0],P1,B0); f2(ACC[1][1],P1,B1); f2(ACC[1][2],P1,B2); f2(ACC[1][3],P1,B3); \
  f2(ACC[2][0],P2,B0); f2(ACC[2][1],P2,B1); f2(ACC[2][2],P2,B2); f2(ACC[2][3],P2,B3); \
  f2(ACC[3][0],P3,B0); f2(ACC[3][1],P3,B1); f2(ACC[3][2],P3,B2); f2(ACC[3][3],P3,B3); \
} while(0)

// -------- K0: rearrange ternary --------
__global__ void k_prep_T(const float* __restrict__ ternary) {
    int idx = blockIdx.x * blockDim.x + threadIdx.x;
    if (idx >= 2*DD*DD*HH) return;
    int c = idx % HH; int t = idx / HH;
    int b = t % DD;   t /= DD;
    int a = t % DD;   int k = t / DD;
    float v = 64.0f * ternary[idx];
    int kc = k*HH + c;
    g_Tr [(kc*DD + a)*DD + b] = v;
    g_Trt[(kc*DD + b)*DD + a] = v;
}

// -------- K1: p = softmax_d(q_z)*mask; writes P and P^T --------
__global__ void k_softmax_p(const float* __restrict__ x, const int* __restrict__ mask, int use_g) {
    int gw = (blockIdx.x * blockDim.x + threadIdx.x) >> 5;
    int lane = threadIdx.x & 31;
    if (gw >= NROW) return;
    int base = gw * DD;
    float v0 = x[base + lane], v1 = x[base + lane + 32];
    if (use_g) {
        #pragma unroll
        for (int g = 0; g < 12; g++) {
            v0 += g_Gpart[g*NELT + base + lane];
            v1 += g_Gpart[g*NELT + base + lane + 32];
        }
        v0 *= (1.0f/64.0f); v1 *= (1.0f/64.0f);
    }
    float m = fmaxf(v0, v1);
    #pragma unroll
    for (int off = 16; off; off >>= 1) m = fmaxf(m, __shfl_xor_sync(0xffffffffu, m, off));
    float e0 = __expf(v0 - m), e1 = __expf(v1 - m);
    float s = e0 + e1;
    #pragma unroll
    for (int off = 16; off; off >>= 1) s += __shfl_xor_sync(0xffffffffu, s, off);
    float mm = (mask[gw] != 0) ? 1.0f : 0.0f;
    float inv = mm / s;
    float p0 = e0 * inv, p1 = e1 * inv;
    g_P[base + lane]      = p0;
    g_P[base + lane + 32] = p1;
    int z = gw >> 9, i = gw & 511;
    g_Pt[(z*DD + lane     )*LL + i] = p0;
    g_Pt[(z*DD + lane + 32)*LL + i] = p1;
}

// -------- K2: fused A + scores + online softmax stats --------
extern __shared__ float smp[];
__global__ void __launch_bounds__(128) k_scoresA() {
    float* sA0 = smp;
    float* sA1 = smp + 64*SP;
    float* sPjBuf[2] = { smp + 2*64*SP, smp + 3*64*SP };
    int i0 = blockIdx.x*64, c = blockIdx.y, z = blockIdx.z;
    int tid = threadIdx.x, tx = tid & 15, ty = tid >> 4;

    // ---- prologue: A0 = Pt_tile @ T[c], A1 = Pt_tile @ T[HH+c], both into smem
    {
        float* sPt = sPjBuf[0];
        float* sT  = sPjBuf[1];      // stride 64, 16KB
        for (int t = tid; t < 1024; t += 128) {
            int r = t >> 4, q = (t & 15) << 2;
            *(float4*)&sPt[r*SP+q] = *(const float4*)&g_Pt[(z*DD + r)*LL + i0 + q];
            *(float4*)&sT [r*64+q] = *(const float4*)&g_Tr[(c*DD + r)*DD + q];
        }
        __syncthreads();
        #pragma unroll
        for (int ph = 0; ph < 2; ph++) {
            u64 acc[4][4] = {};
            #pragma unroll 8
            for (int a = 0; a < 64; a++) {
                ulonglong2 p01 = *(const ulonglong2*)&sPt[a*SP + ty*8];
                ulonglong2 p23 = *(const ulonglong2*)&sPt[a*SP + ty*8 + 4];
                float4 fp = *(const float4*)&sT[a*64 + tx*4];
                u64 b0=bc2(fp.x), b1=bc2(fp.y), b2=bc2(fp.z), b3=bc2(fp.w);
                STEP4(acc, p01.x, p01.y, p23.x, p23.y, b0, b1, b2, b3);
            }
            __syncthreads();                 // all reads of sT done
            float* dst0 = ph ? sA1 : sA0;
            #pragma unroll
            for (int s = 0; s < 4; s++) {
                float* dst = &dst0[(tx*4+s)*SP + ty*8];
                ((ulonglong2*)dst)[0] = make_ulonglong2(acc[0][s], acc[1][s]);
                ((ulonglong2*)dst)[1] = make_ulonglong2(acc[2][s], acc[3][s]);
            }
            if (ph == 0) {
                for (int t = tid; t < 1024; t += 128) {
                    int r = t >> 4, q = (t & 15) << 2;
                    *(float4*)&sT[r*64+q] = *(const float4*)&g_Tr[((HH+c)*DD + r)*DD + q];
                }
                __syncthreads();
            }
        }
        __syncthreads();                     // sPt/sT regions free for Pj pipeline
    }

    // ---- pipelined scores loop
    for (int t = tid; t < 1024; t += 128) {  // issue Pj(0)
        int b = t >> 4, q = (t & 15) << 2;
        cpa16(smaddr(&sPjBuf[0][b*SP+q]), &g_Pt[(z*DD + b)*LL + 0 + q]);
    }
    cpcommit();

    float m[8], ss[8];
    #pragma unroll
    for (int r = 0; r < 8; r++) { m[r] = -1e30f; ss[r] = 0.0f; }

    for (int jt = 0; jt < 8; jt++) {
        int j0 = jt * 64;
        cpwait0(); __syncthreads();
        if (jt < 7) {
            float* nb = sPjBuf[(jt+1)&1];
            for (int t = tid; t < 1024; t += 128) {
                int b = t >> 4, q = (t & 15) << 2;
                cpa16(smaddr(&nb[b*SP+q]), &g_Pt[(z*DD + b)*LL + j0 + 64 + q]);
            }
            cpcommit();
        }
        const float* sPj = sPjBuf[jt&1];
        float v[8][4];
        if (j0 != i0) {
            const float* sA = (j0 > i0) ? sA0 : sA1;
            u64 acc[4][4] = {};
            #pragma unroll 8
            for (int b = 0; b < 64; b++) {
                ulonglong2 a01 = *(const ulonglong2*)&sA[b*SP + ty*8];
                ulonglong2 a23 = *(const ulonglong2*)&sA[b*SP + ty*8 + 4];
                float4 fp = *(const float4*)&sPj[b*SP + tx*4];
                u64 b0=bc2(fp.x), b1=bc2(fp.y), b2=bc2(fp.z), b3=bc2(fp.w);
                STEP4(acc, a01.x, a01.y, a23.x, a23.y, b0, b1, b2, b3);
            }
            #pragma unroll
            for (int rp = 0; rp < 4; rp++)
                #pragma unroll
                for (int s = 0; s < 4; s++) {
                    float2 f = up2(acc[rp][s]);
                    v[2*rp][s] = f.x; v[2*rp+1][s] = f.y;
                }
        } else {
            u64 A0[4][4] = {}, A1[4][4] = {};
            #pragma unroll 4
            for (int b = 0; b < 64; b++) {
                ulonglong2 a01 = *(const ulonglong2*)&sA0[b*SP + ty*8];
                ulonglong2 a23 = *(const ulonglong2*)&sA0[b*SP + ty*8 + 4];
                ulonglong2 c01 = *(const ulonglong2*)&sA1[b*SP + ty*8];
                ulonglong2 c23 = *(const ulonglong2*)&sA1[b*SP + ty*8 + 4];
                float4 fp = *(const float4*)&sPj[b*SP + tx*4];
                u64 b0=bc2(fp.x), b1=bc2(fp.y), b2=bc2(fp.z), b3=bc2(fp.w);
                STEP4(A0, a01.x, a01.y, a23.x, a23.y, b0, b1, b2, b3);
                STEP4(A1, c01.x, c01.y, c23.x, c23.y, b0, b1, b2, b3);
            }
            #pragma unroll
            for (int rp = 0; rp < 4; rp++)
                #pragma unroll
                for (int s = 0; s < 4; s++) {
                    float2 f0 = up2(A0[rp][s]), f1 = up2(A1[rp][s]);
                    int gj = tx*4 + s;
                    int giA = ty*8 + 2*rp, giB = giA + 1;
                    v[2*rp  ][s] = (gj > giA) ? f0.x : ((gj < giA) ? f1.x : 0.0f);
                    v[2*rp+1][s] = (gj > giB) ? f0.y : ((gj < giB) ? f1.y : 0.0f);
                }
        }
        #pragma unroll
        for (int r = 0; r < 8; r++) {
            int gi = i0 + ty*8 + r;
            *(float4*)&g_S[((z*HH + c)*LL + gi)*LL + j0 + tx*4] =
                make_float4(v[r][0], v[r][1], v[r][2], v[r][3]);
            float tm = fmaxf(fmaxf(v[r][0], v[r][1]), fmaxf(v[r][2], v[r][3]));
            float nm = fmaxf(m[r], tm);
            ss[r] = ss[r] * __expf(m[r] - nm)
                  + __expf(v[r][0]-nm) + __expf(v[r][1]-nm)
                  + __expf(v[r][2]-nm) + __expf(v[r][3]-nm);
            m[r] = nm;
        }
    }
    #pragma unroll
    for (int r = 0; r < 8; r++) {
        float mr = m[r], sr = ss[r];
        #pragma unroll
        for (int off = 1; off < 16; off <<= 1) {
            float om = __shfl_xor_sync(0xffffffffu, mr, off);
            float os = __shfl_xor_sync(0xffffffffu, sr, off);
            float nm = fmaxf(mr, om);
            sr = sr * __expf(mr - nm) + os * __expf(om - nm);
            mr = nm;
        }
        if (tx == 0) {
            int ridx = (z*HH + c)*LL + i0 + ty*8 + r;
            g_stats[ridx*2]     = mr;
            g_stats[ridx*2 + 1] = sr;
        }
    }
}

// -------- K3: fused normalize + W + G-partial --------
__global__ void __launch_bounds__(128) k_probs_WG() {
    extern __shared__ float smq[];
    float* sSt   = smq;                    // 4608
    float* sSraw = smq + 64*SP;            // 4352 (stride 68)
    float* sVBuf[2] = { smq + 64*SP + 64*68, smq + 2*64*SP + 64*68 };
    float* sM  = smq + 3*64*SP + 64*68;
    float* sIs = sM + 64;
    int i0 = blockIdx.x*64, c = blockIdx.y, z = blockIdx.z;
    int tid = threadIdx.x, tx = tid & 15, ty = tid >> 4;

    // issue S(0), V(0)
    for (int t = tid; t < 1024; t += 128) {
        int r = t >> 4, q = (t & 15) << 2;
        cpa16(smaddr(&sSraw[r*68 + q]), &g_S[((z*HH + c)*LL + i0 + r)*LL + 0 + q]);
        cpa16(smaddr(&sVBuf[0][r*SP + q]), &g_P[(z*LL + 0 + r)*DD + q]);
    }
    cpcommit();
    if (tid < 64) {
        int ridx = (z*HH + c)*LL + i0 + tid;
        sM[tid]  = g_stats[ridx*2];
        sIs[tid] = 1.0f / g_stats[ridx*2 + 1];
    }

    u64 aU[4][4] = {}, aL[4][4] = {};
    for (int jt = 0; jt < 8; jt++) {
        int j0 = jt * 64;
        cpwait0(); __syncthreads();
        // transform raw S -> normalized probs, transposed+swizzled
        for (int t = tid; t < 1024; t += 128) {
            int i  = (t & 7) | (((t >> 5) & 7) << 3);
            int j4 = ((t >> 3) & 3) | (((t >> 8) & 3) << 2);
            float4 s4 = *(const float4*)&sSraw[i*68 + j4*4];
            float mi = sM[i], isi = sIs[i];
            int ic = i ^ ((j4 & 3) << 3);
            sSt[(j4*4+0)*SP + ic] = __expf(s4.x - mi) * isi;
            sSt[(j4*4+1)*SP + ic] = __expf(s4.y - mi) * isi;
            sSt[(j4*4+2)*SP + ic] = __expf(s4.z - mi) * isi;
            sSt[(j4*4+3)*SP + ic] = __expf(s4.w - mi) * isi;
        }
        __syncthreads();
        if (jt < 7) {
            float* nv = sVBuf[(jt+1)&1];
            for (int t = tid; t < 1024; t += 128) {
                int r = t >> 4, q = (t & 15) << 2;
                cpa16(smaddr(&sSraw[r*68 + q]), &g_S[((z*HH + c)*LL + i0 + r)*LL + j0 + 64 + q]);
                cpa16(smaddr(&nv[r*SP + q]), &g_P[(z*LL + j0 + 64 + r)*DD + q]);
            }
            cpcommit();
        }
        const float* sV = sVBuf[jt&1];
        if (j0 != i0) {
            u64 (*A)[4] = (j0 > i0) ? aU : aL;
            #pragma unroll 8
            for (int j = 0; j < 64; j++) {
                int base = (ty*8) ^ (((j >> 2) & 3) << 3);
                ulonglong2 p01 = *(const ulonglong2*)&sSt[j*SP + base];
                ulonglong2 p23 = *(const ulonglong2*)&sSt[j*SP + base + 4];
                float4 fv = *(const float4*)&sV[j*SP + tx*4];
                u64 b0=bc2(fv.x), b1=bc2(fv.y), b2=bc2(fv.z), b3=bc2(fv.w);
                STEP4(A, p01.x, p01.y, p23.x, p23.y, b0, b1, b2, b3);
            }
        } else {
            #pragma unroll 4
            for (int j = 0; j < 64; j++) {
                int base = (ty*8) ^ (((j >> 2) & 3) << 3);
                ulonglong2 p01 = *(const ulonglong2*)&sSt[j*SP + base];
                ulonglong2 p23 = *(const ulonglong2*)&sSt[j*SP + base + 4];
                float4 fv = *(const float4*)&sV[j*SP + tx*4];
                u64 b0=bc2(fv.x), b1=bc2(fv.y), b2=bc2(fv.z), b3=bc2(fv.w);
                u64 pa[4] = {p01.x, p01.y, p23.x, p23.y};
                #pragma unroll
                for (int rp = 0; rp < 4; rp++) {
                    int il = ty*8 + rp*2;
                    u64 f = pa[rp];
                    u64 fL = (j < il)   ? f : ((j == il)   ? (f & 0xFFFFFFFF00000000ULL) : 0ULL);
                    u64 fU = (j > il+1) ? f : ((j == il+1) ? (f & 0x00000000FFFFFFFFULL) : 0ULL);
                    f2(aL[rp][0], fL, b0); f2(aL[rp][1], fL, b1); f2(aL[rp][2], fL, b2); f2(aL[rp][3], fL, b3);
                    f2(aU[rp][0], fU, b0); f2(aU[rp][1], fU, b1); f2(aU[rp][2], fU, b2); f2(aU[rp][3], fU, b3);
                }
            }
        }
    }
    // ---- epilogue: G_c = W_U @ Trt[c] + W_L @ Trt[HH+c]
    __syncthreads();
    float* sWU = sVBuf[0];
    float* sWL = sVBuf[1];
    float* sTU = sSt;                       // stride 64
    float* sTL = sSraw;                     // stride 64
    #pragma unroll
    for (int s = 0; s < 4; s++) {
        float* dU = &sWU[(tx*4+s)*SP + ty*8];
        ((ulonglong2*)dU)[0] = make_ulonglong2(aU[0][s], aU[1][s]);
        ((ulonglong2*)dU)[1] = make_ulonglong2(aU[2][s], aU[3][s]);
        float* dL = &sWL[(tx*4+s)*SP + ty*8];
        ((ulonglong2*)dL)[0] = make_ulonglong2(aL[0][s], aL[1][s]);
        ((ulonglong2*)dL)[1] = make_ulonglong2(aL[2][s], aL[3][s]);
    }
    for (int t = tid; t < 1024; t += 128) {
        int r = t >> 4, q = (t & 15) << 2;
        *(float4*)&sTU[r*64+q] = *(const float4*)&g_Trt[(c*DD + r)*DD + q];
        *(float4*)&sTL[r*64+q] = *(const float4*)&g_Trt[((HH+c)*DD + r)*DD + q];
    }
    __syncthreads();
    u64 acc[4][4] = {};
    #pragma unroll 4
    for (int b = 0; b < 64; b++) {
        ulonglong2 w01 = *(const ulonglong2*)&sWU[b*SP + ty*8];
        ulonglong2 w23 = *(const ulonglong2*)&sWU[b*SP + ty*8 + 4];
        float4 ft = *(const float4*)&sTU[b*64 + tx*4];
        u64 b0=bc2(ft.x), b1=bc2(ft.y), b2=bc2(ft.z), b3=bc2(ft.w);
        STEP4(acc, w01.x, w01.y, w23.x, w23.y, b0, b1, b2, b3);
        ulonglong2 y01 = *(const ulonglong2*)&sWL[b*SP + ty*8];
        ulonglong2 y23 = *(const ulonglong2*)&sWL[b*SP + ty*8 + 4];
        float4 fl = *(const float4*)&sTL[b*64 + tx*4];
        u64 c0=bc2(fl.x), c1=bc2(fl.y), c2=bc2(fl.z), c3=bc2(fl.w);
        STEP4(acc, y01.x, y01.y, y23.x, y23.y, c0, c1, c2, c3);
    }
    #pragma unroll
    for (int rp = 0; rp < 4; rp++) {
        float2 x0 = up2(acc[rp][0]), x1 = up2(acc[rp][1]);
        float2 x2 = up2(acc[rp][2]), x3 = up2(acc[rp][3]);
        int i = i0 + ty*8 + rp*2;
        *(float4*)&g_Gpart[(c*NROW + z*LL + i    )*DD + tx*4] = make_float4(x0.x, x1.x, x2.x, x3.x);
        *(float4*)&g_Gpart[(c*NROW + z*LL + i + 1)*DD + tx*4] = make_float4(x0.y, x1.y, x2.y, x3.y);
    }
}

// -------- K4: out = (x + sum Gpart) / 64 --------
__global__ void k_final(const float* __restrict__ x, float* __restrict__ out) {
    int idx = blockIdx.x * blockDim.x + threadIdx.x;
    if (idx >= NELT) return;
    float v = x[idx];
    #pragma unroll
    for (int g = 0; g < 12; g++) v += g_Gpart[g*NELT + idx];
    out[idx] = v * (1.0f/64.0f);
}

extern "C" void kernel_launch(void* const* d_in, const int* in_sizes, int n_in,
                              void* d_out, int out_size) {
    const float* x       = (const float*)d_in[0];
    const int*   mask    = (const int*)d_in[1];
    const float* ternary = (const float*)d_in[2];
    for (int i = 0; i < n_in; i++) {
        if      (in_sizes[i] == NELT)        x       = (const float*)d_in[i];
        else if (in_sizes[i] == BB*LL)       mask    = (const int*)d_in[i];
        else if (in_sizes[i] == 2*DD*DD*HH)  ternary = (const float*)d_in[i];
    }
    const int SMEM_SA = 4*64*SP*4;                    // 73728 B
    const int SMEM_WG = (3*64*SP + 64*68 + 128)*4;    // 73216 B
    cudaFuncSetAttribute(k_scoresA,  cudaFuncAttributeMaxDynamicSharedMemorySize, SMEM_SA);
    cudaFuncSetAttribute(k_probs_WG, cudaFuncAttributeMaxDynamicSharedMemorySize, SMEM_WG);

    k_prep_T<<<96, 1024>>>(ternary);
    for (int it = 0; it < 4; it++) {
        k_softmax_p<<<NROW/4, 128>>>(x, mask, it > 0 ? 1 : 0);
        k_scoresA <<<dim3(8, HH, BB), 128, SMEM_SA>>>();
        k_probs_WG<<<dim3(8, HH, BB), 128, SMEM_WG>>>();
    }
    k_final<<<(NELT + 255)/256, 256>>>(x, (float*)d_out);
}

// round 4
// speedup vs baseline: 1.3196x; 1.0785x over previous
#include <cuda_runtime.h>

// HeadProbEncoder: B=8, L=512, d=64, n_head=12, K=2 triangles, 4 iterations.
// Round 4: single-pass flash-style fusion — A-prologue, S tiles, online softmax,
// W accumulation with rescale, and G epilogue all in one kernel. g_S eliminated.

#define BB 8
#define LL 512
#define DD 64
#define HH 12
#define KH 24
#define NROW (BB*LL)
#define NELT (BB*LL*DD)
#define SA 68                 // stride for [b][i]-style tiles
#define SS 72                 // stride for swizzled exp(S) tile

typedef unsigned long long u64;

// -------- scratch --------
__device__ float g_P [NELT];          // [z][i][b]
__device__ float g_Pt[BB*DD*LL];      // [z][b][i]
__device__ float g_Tr [KH*DD*DD];     // [kc][a][b]
__device__ float g_Trt[KH*DD*DD];     // [kc][b][a]
__device__ float g_Gpart[12*NELT];    // per-c G partials

__device__ __forceinline__ u64 bc2(float v){ u64 r; asm("mov.b64 %0,{%1,%1};":"=l"(r):"f"(v)); return r; }
__device__ __forceinline__ u64 pk2(float lo, float hi){ u64 r; asm("mov.b64 %0,{%1,%2};":"=l"(r):"f"(lo),"f"(hi)); return r; }
__device__ __forceinline__ void f2(u64 &d, u64 a, u64 b){ asm("fma.rn.f32x2 %0,%1,%2,%0;":"+l"(d):"l"(a),"l"(b)); }
__device__ __forceinline__ void m2(u64 &d, u64 s){ asm("mul.rn.f32x2 %0,%0,%1;":"+l"(d):"l"(s)); }
__device__ __forceinline__ float2 up2(u64 v){ float2 f; asm("mov.b64 {%0,%1},%2;":"=f"(f.x),"=f"(f.y):"l"(v)); return f; }
__device__ __forceinline__ unsigned smaddr(const void* p){ return (unsigned)__cvta_generic_to_shared(p); }
__device__ __forceinline__ void cpa16(unsigned s, const void* g){ asm volatile("cp.async.cg.shared.global [%0],[%1],16;"::"r"(s),"l"(g):"memory"); }
__device__ __forceinline__ void cpcommit(){ asm volatile("cp.async.commit_group;":::"memory"); }
__device__ __forceinline__ void cpwait0(){ asm volatile("cp.async.wait_group 0;":::"memory"); }
__device__ __forceinline__ void cpwait1(){ asm volatile("cp.async.wait_group 1;":::"memory"); }

#define STEP4(ACC,P0,P1,P2,P3,B0,B1,B2,B3) do{ \
  f2(ACC[0][0],P0,B0); f2(ACC[0][1],P0,B1); f2(ACC[0][2],P0,B2); f2(ACC[0][3],P0,B3); \
  f2(ACC[1][0],P1,B0); f2(ACC[1][1],P1,B1); f2(ACC[1][2],P1,B2); f2(ACC[1][3],P1,B3); \
  f2(ACC[2][0],P2,B0); f2(ACC[2][1],P2,B1); f2(ACC[2][2],P2,B2); f2(ACC[2][3],P2,B3); \
  f2(ACC[3][0],P3,B0); f2(ACC[3][1],P3,B1); f2(ACC[3][2],P3,B2); f2(ACC[3][3],P3,B3); \
} while(0)

// -------- K0: rearrange ternary --------
__global__ void k_prep_T(const float* __restrict__ ternary) {
    int idx = blockIdx.x * blockDim.x + threadIdx.x;
    if (idx >= 2*DD*DD*HH) return;
    int c = idx % HH; int t = idx / HH;
    int b = t % DD;   t /= DD;
    int a = t % DD;   int k = t / DD;
    float v = 64.0f * ternary[idx];
    int kc = k*HH + c;
    g_Tr [(kc*DD + a)*DD + b] = v;
    g_Trt[(kc*DD + b)*DD + a] = v;
}

// -------- K1: p = softmax_d(q_z)*mask; writes P and P^T --------
__global__ void k_softmax_p(const float* __restrict__ x, const int* __restrict__ mask, int use_g) {
    int gw = (blockIdx.x * blockDim.x + threadIdx.x) >> 5;
    int lane = threadIdx.x & 31;
    if (gw >= NROW) return;
    int base = gw * DD;
    float v0 = x[base + lane], v1 = x[base + lane + 32];
    if (use_g) {
        #pragma unroll
        for (int g = 0; g < 12; g++) {
            v0 += g_Gpart[g*NELT + base + lane];
            v1 += g_Gpart[g*NELT + base + lane + 32];
        }
        v0 *= (1.0f/64.0f); v1 *= (1.0f/64.0f);
    }
    float m = fmaxf(v0, v1);
    #pragma unroll
    for (int off = 16; off; off >>= 1) m = fmaxf(m, __shfl_xor_sync(0xffffffffu, m, off));
    float e0 = __expf(v0 - m), e1 = __expf(v1 - m);
    float s = e0 + e1;
    #pragma unroll
    for (int off = 16; off; off >>= 1) s += __shfl_xor_sync(0xffffffffu, s, off);
    float mm = (mask[gw] != 0) ? 1.0f : 0.0f;
    float inv = mm / s;
    float p0 = e0 * inv, p1 = e1 * inv;
    g_P[base + lane]      = p0;
    g_P[base + lane + 32] = p1;
    int z = gw >> 9, i = gw & 511;
    g_Pt[(z*DD + lane     )*LL + i] = p0;
    g_Pt[(z*DD + lane + 32)*LL + i] = p1;
}

// -------- K2: fully fused per-(z,c,i0): A, S tiles, flash softmax, W, G --------
extern __shared__ float smf[];
__global__ void __launch_bounds__(128) k_fused() {
    float* sA0 = smf;                       // [b][i]   stride SA
    float* sA1 = smf +   64*SA;             // [b][i]
    float* sPj = smf + 2*64*SA;             // [b][j]   stride SA (prologue: sT stride 64)
    float* sV  = smf + 3*64*SA;             // [j][b]   stride SA
    float* sSt = smf + 4*64*SA;             // [j][i^swz] stride SS (prologue: sPt)
    int i0 = blockIdx.x*64, c = blockIdx.y, z = blockIdx.z;
    int tid = threadIdx.x, tx = tid & 15, ty = tid >> 4;

    // V(0) prefetch can start immediately (sV untouched by prologue)
    for (int t = tid; t < 1024; t += 128) {
        int r = t >> 4, q = (t & 15) << 2;
        cpa16(smaddr(&sV[r*SA + q]), &g_P[(z*LL + r)*DD + q]);
    }
    cpcommit();

    // ---- prologue: A0 = Pt_tile @ T[c], A1 = Pt_tile @ T[HH+c]
    {
        float* sPt = sSt;                   // [a][i] stride SS
        float* sT  = sPj;                   // [a][b] stride 64
        for (int t = tid; t < 1024; t += 128) {
            int r = t >> 4, q = (t & 15) << 2;
            *(float4*)&sPt[r*SS+q] = *(const float4*)&g_Pt[(z*DD + r)*LL + i0 + q];
            *(float4*)&sT [r*64+q] = *(const float4*)&g_Tr[(c*DD + r)*DD + q];
        }
        __syncthreads();
        #pragma unroll
        for (int ph = 0; ph < 2; ph++) {
            u64 acc[4][4] = {};
            #pragma unroll 8
            for (int a = 0; a < 64; a++) {
                ulonglong2 p01 = *(const ulonglong2*)&sPt[a*SS + ty*8];
                ulonglong2 p23 = *(const ulonglong2*)&sPt[a*SS + ty*8 + 4];
                float4 fp = *(const float4*)&sT[a*64 + tx*4];
                u64 b0=bc2(fp.x), b1=bc2(fp.y), b2=bc2(fp.z), b3=bc2(fp.w);
                STEP4(acc, p01.x, p01.y, p23.x, p23.y, b0, b1, b2, b3);
            }
            __syncthreads();
            float* dst0 = ph ? sA1 : sA0;
            #pragma unroll
            for (int s = 0; s < 4; s++) {
                float* dst = &dst0[(tx*4+s)*SA + ty*8];
                ((ulonglong2*)dst)[0] = make_ulonglong2(acc[0][s], acc[1][s]);
                ((ulonglong2*)dst)[1] = make_ulonglong2(acc[2][s], acc[3][s]);
            }
            if (ph == 0) {
                for (int t = tid; t < 1024; t += 128) {
                    int r = t >> 4, q = (t & 15) << 2;
                    *(float4*)&sT[r*64+q] = *(const float4*)&g_Tr[((HH+c)*DD + r)*DD + q];
                }
                __syncthreads();
            }
        }
        __syncthreads();                    // sPj/sSt free now
    }

    // issue Pj(0)
    for (int t = tid; t < 1024; t += 128) {
        int r = t >> 4, q = (t & 15) << 2;
        cpa16(smaddr(&sPj[r*SA + q]), &g_Pt[(z*DD + r)*LL + q]);
    }
    cpcommit();   // pending: {V0, Pj0}

    float m[8], ss[8], scv[8];
    #pragma unroll
    for (int r = 0; r < 8; r++) { m[r] = -1e30f; ss[r] = 0.0f; }
    u64 aU[4][4] = {}, aL[4][4] = {};

    for (int jt = 0; jt < 8; jt++) {
        int j0 = jt * 64;
        if (jt == 0) cpwait0(); else cpwait1();   // Pj[jt] ready
        __syncthreads();

        // ---- S GEMM
        float v[8][4];
        if (j0 != i0) {
            const float* sA = (j0 > i0) ? sA0 : sA1;
            u64 acc[4][4] = {};
            #pragma unroll 8
            for (int b = 0; b < 64; b++) {
                ulonglong2 a01 = *(const ulonglong2*)&sA[b*SA + ty*8];
                ulonglong2 a23 = *(const ulonglong2*)&sA[b*SA + ty*8 + 4];
                float4 fp = *(const float4*)&sPj[b*SA + tx*4];
                u64 b0=bc2(fp.x), b1=bc2(fp.y), b2=bc2(fp.z), b3=bc2(fp.w);
                STEP4(acc, a01.x, a01.y, a23.x, a23.y, b0, b1, b2, b3);
            }
            #pragma unroll
            for (int rp = 0; rp < 4; rp++)
                #pragma unroll
                for (int s = 0; s < 4; s++) {
                    float2 f = up2(acc[rp][s]);
                    v[2*rp][s] = f.x; v[2*rp+1][s] = f.y;
                }
        } else {
            u64 A0[4][4] = {}, A1[4][4] = {};
            #pragma unroll 4
            for (int b = 0; b < 64; b++) {
                ulonglong2 a01 = *(const ulonglong2*)&sA0[b*SA + ty*8];
                ulonglong2 a23 = *(const ulonglong2*)&sA0[b*SA + ty*8 + 4];
                ulonglong2 c01 = *(const ulonglong2*)&sA1[b*SA + ty*8];
                ulonglong2 c23 = *(const ulonglong2*)&sA1[b*SA + ty*8 + 4];
                float4 fp = *(const float4*)&sPj[b*SA + tx*4];
                u64 b0=bc2(fp.x), b1=bc2(fp.y), b2=bc2(fp.z), b3=bc2(fp.w);
                STEP4(A0, a01.x, a01.y, a23.x, a23.y, b0, b1, b2, b3);
                STEP4(A1, c01.x, c01.y, c23.x, c23.y, b0, b1, b2, b3);
            }
            #pragma unroll
            for (int rp = 0; rp < 4; rp++)
                #pragma unroll
                for (int s = 0; s < 4; s++) {
                    float2 f0 = up2(A0[rp][s]), f1 = up2(A1[rp][s]);
                    int gj = tx*4 + s;
                    int giA = ty*8 + 2*rp, giB = giA + 1;
                    v[2*rp  ][s] = (gj > giA) ? f0.x : ((gj < giA) ? f1.x : 0.0f);
                    v[2*rp+1][s] = (gj > giB) ? f0.y : ((gj < giB) ? f1.y : 0.0f);
                }
        }

        // ---- flash update: shared row max, rescale stats, write exp tile
        #pragma unroll
        for (int r = 0; r < 8; r++) {
            float tm = fmaxf(fmaxf(v[r][0], v[r][1]), fmaxf(v[r][2], v[r][3]));
            #pragma unroll
            for (int off = 1; off < 16; off <<= 1)
                tm = fmaxf(tm, __shfl_xor_sync(0xffffffffu, tm, off));
            float nm = fmaxf(m[r], tm);
            float sc = __expf(m[r] - nm);
            float e0 = __expf(v[r][0]-nm), e1 = __expf(v[r][1]-nm);
            float e2 = __expf(v[r][2]-nm), e3 = __expf(v[r][3]-nm);
            ss[r] = ss[r]*sc + e0+e1+e2+e3;
            m[r] = nm; scv[r] = sc;
            int ic = (ty*8+r) ^ ((tx&3) << 3);
            int gi = ty*8 + r;
            if (j0 == i0) {   // zero the diagonal element (excluded from W)
                if (tx*4+0 == gi) e0 = 0.0f;
                if (tx*4+1 == gi) e1 = 0.0f;
                if (tx*4+2 == gi) e2 = 0.0f;
                if (tx*4+3 == gi) e3 = 0.0f;
            }
            sSt[(tx*4+0)*SS + ic] = e0;
            sSt[(tx*4+1)*SS + ic] = e1;
            sSt[(tx*4+2)*SS + ic] = e2;
            sSt[(tx*4+3)*SS + ic] = e3;
        }
        __syncthreads();                    // sSt complete; sPj free

        if (jt < 7) {
            for (int t = tid; t < 1024; t += 128) {
                int r = t >> 4, q = (t & 15) << 2;
                cpa16(smaddr(&sPj[r*SA + q]), &g_Pt[(z*DD + r)*LL + j0 + 64 + q]);
            }
            cpcommit();                     // pending: {V[jt], Pj[jt+1]}
        }

        // rescale W accumulators (independent of smem)
        #pragma unroll
        for (int rp = 0; rp < 4; rp++) {
            u64 sc2 = pk2(scv[2*rp], scv[2*rp+1]);
            #pragma unroll
            for (int s = 0; s < 4; s++) { m2(aU[rp][s], sc2); m2(aL[rp][s], sc2); }
        }

        cpwait1();                          // V[jt] ready
        __syncthreads();

        // ---- W GEMM: accumulate exp tile @ V
        if (j0 != i0) {
            u64 (*A)[4] = (j0 > i0) ? aU : aL;
            #pragma unroll 8
            for (int j = 0; j < 64; j++) {
                int base = (ty*8) ^ (((j >> 2) & 3) << 3);
                ulonglong2 p01 = *(const ulonglong2*)&sSt[j*SS + base];
                ulonglong2 p23 = *(const ulonglong2*)&sSt[j*SS + base + 4];
                float4 fv = *(const float4*)&sV[j*SA + tx*4];
                u64 b0=bc2(fv.x), b1=bc2(fv.y), b2=bc2(fv.z), b3=bc2(fv.w);
                STEP4(A, p01.x, p01.y, p23.x, p23.y, b0, b1, b2, b3);
            }
        } else {
            #pragma unroll 4
            for (int j = 0; j < 64; j++) {
                int base = (ty*8) ^ (((j >> 2) & 3) << 3);
                ulonglong2 p01 = *(const ulonglong2*)&sSt[j*SS + base];
                ulonglong2 p23 = *(const ulonglong2*)&sSt[j*SS + base + 4];
                float4 fv = *(const float4*)&sV[j*SA + tx*4];
                u64 b0=bc2(fv.x), b1=bc2(fv.y), b2=bc2(fv.z), b3=bc2(fv.w);
                u64 pa[4] = {p01.x, p01.y, p23.x, p23.y};
                #pragma unroll
                for (int rp = 0; rp < 4; rp++) {
                    int il = ty*8 + rp*2;
                    u64 f = pa[rp];
                    u64 fL = (j < il)   ? f : ((j == il)   ? (f & 0xFFFFFFFF00000000ULL) : 0ULL);
                    u64 fU = (j > il+1) ? f : ((j == il+1) ? (f & 0x00000000FFFFFFFFULL) : 0ULL);
                    f2(aL[rp][0], fL, b0); f2(aL[rp][1], fL, b1); f2(aL[rp][2], fL, b2); f2(aL[rp][3], fL, b3);
                    f2(aU[rp][0], fU, b0); f2(aU[rp][1], fU, b1); f2(aU[rp][2], fU, b2); f2(aU[rp][3], fU, b3);
                }
            }
        }
        __syncthreads();                    // done reading sV

        if (jt < 7) {
            for (int t = tid; t < 1024; t += 128) {
                int r = t >> 4, q = (t & 15) << 2;
                cpa16(smaddr(&sV[r*SA + q]), &g_P[(z*LL + j0 + 64 + r)*DD + q]);
            }
            cpcommit();                     // pending: {Pj[jt+1], V[jt+1]}
        }
    }

    // ---- normalize W by 1/sum_exp (sum partial ss across the 16 tx lanes)
    #pragma unroll
    for (int r = 0; r < 8; r++) {
        float sr = ss[r];
        #pragma unroll
        for (int off = 1; off < 16; off <<= 1)
            sr += __shfl_xor_sync(0xffffffffu, sr, off);
        ss[r] = 1.0f / sr;
    }
    #pragma unroll
    for (int rp = 0; rp < 4; rp++) {
        u64 iv2 = pk2(ss[2*rp], ss[2*rp+1]);
        #pragma unroll
        for (int s = 0; s < 4; s++) { m2(aU[rp][s], iv2); m2(aL[rp][s], iv2); }
    }

    // ---- epilogue: G_c = W_U @ Trt[c] + W_L @ Trt[HH+c]
    float* sWU = sA0;     // overwrite A tiles with W tiles [b][i]
    float* sWL = sA1;
    float* sTU = sSt;     // stride 64
    float* sTL = sPj;     // stride 64
    #pragma unroll
    for (int s = 0; s < 4; s++) {
        float* dU = &sWU[(tx*4+s)*SA + ty*8];
        ((ulonglong2*)dU)[0] = make_ulonglong2(aU[0][s], aU[1][s]);
        ((ulonglong2*)dU)[1] = make_ulonglong2(aU[2][s], aU[3][s]);
        float* dL = &sWL[(tx*4+s)*SA + ty*8];
        ((ulonglong2*)dL)[0] = make_ulonglong2(aL[0][s], aL[1][s]);
        ((ulonglong2*)dL)[1] = make_ulonglong2(aL[2][s], aL[3][s]);
    }
    for (int t = tid; t < 1024; t += 128) {
        int r = t >> 4, q = (t & 15) << 2;
        *(float4*)&sTU[r*64+q] = *(const float4*)&g_Trt[(c*DD + r)*DD + q];
        *(float4*)&sTL[r*64+q] = *(const float4*)&g_Trt[((HH+c)*DD + r)*DD + q];
    }
    __syncthreads();
    u64 acc[4][4] = {};
    #pragma unroll 4
    for (int b = 0; b < 64; b++) {
        ulonglong2 w01 = *(const ulonglong2*)&sWU[b*SA + ty*8];
        ulonglong2 w23 = *(const ulonglong2*)&sWU[b*SA + ty*8 + 4];
        float4 ft = *(const float4*)&sTU[b*64 + tx*4];
        u64 b0=bc2(ft.x), b1=bc2(ft.y), b2=bc2(ft.z), b3=bc2(ft.w);
        STEP4(acc, w01.x, w01.y, w23.x, w23.y, b0, b1, b2, b3);
        ulonglong2 y01 = *(const ulonglong2*)&sWL[b*SA + ty*8];
        ulonglong2 y23 = *(const ulonglong2*)&sWL[b*SA + ty*8 + 4];
        float4 fl = *(const float4*)&sTL[b*64 + tx*4];
        u64 c0=bc2(fl.x), c1=bc2(fl.y), c2=bc2(fl.z), c3=bc2(fl.w);
        STEP4(acc, y01.x, y01.y, y23.x, y23.y, c0, c1, c2, c3);
    }
    #pragma unroll
    for (int rp = 0; rp < 4; rp++) {
        float2 x0 = up2(acc[rp][0]), x1 = up2(acc[rp][1]);
        float2 x2 = up2(acc[rp][2]), x3 = up2(acc[rp][3]);
        int i = i0 + ty*8 + rp*2;
        *(float4*)&g_Gpart[(c*NROW + z*LL + i    )*DD + tx*4] = make_float4(x0.x, x1.x, x2.x, x3.x);
        *(float4*)&g_Gpart[(c*NROW + z*LL + i + 1)*DD + tx*4] = make_float4(x0.y, x1.y, x2.y, x3.y);
    }
}

// -------- K3: out = (x + sum Gpart) / 64 --------
__global__ void k_final(const float* __restrict__ x, float* __restrict__ out) {
    int idx = blockIdx.x * blockDim.x + threadIdx.x;
    if (idx >= NELT) return;
    float v = x[idx];
    #pragma unroll
    for (int g = 0; g < 12; g++) v += g_Gpart[g*NELT + idx];
    out[idx] = v * (1.0f/64.0f);
}

extern "C" void kernel_launch(void* const* d_in, const int* in_sizes, int n_in,
                              void* d_out, int out_size) {
    const float* x       = (const float*)d_in[0];
    const int*   mask    = (const int*)d_in[1];
    const float* ternary = (const float*)d_in[2];
    for (int i = 0; i < n_in; i++) {
        if      (in_sizes[i] == NELT)        x       = (const float*)d_in[i];
        else if (in_sizes[i] == BB*LL)       mask    = (const int*)d_in[i];
        else if (in_sizes[i] == 2*DD*DD*HH)  ternary = (const float*)d_in[i];
    }
    const int SMEM_F = (4*64*SA + 64*SS) * 4;   // 88064 B
    cudaFuncSetAttribute(k_fused, cudaFuncAttributeMaxDynamicSharedMemorySize, SMEM_F);

    k_prep_T<<<96, 1024>>>(ternary);
    for (int it = 0; it < 4; it++) {
        k_softmax_p<<<NROW/4, 128>>>(x, mask, it > 0 ? 1 : 0);
        k_fused<<<dim3(8, HH, BB), 128, SMEM_F>>>();
    }
    k_final<<<(NELT + 255)/256, 256>>>(x, (float*)d_out);
}

// round 6
// speedup vs baseline: 1.3962x; 1.0581x over previous
#include <cuda_runtime.h>

// HeadProbEncoder: B=8, L=512, d=64, n_head=12, K=2 triangles, 4 iterations.
// Round 5 (resubmit after infra failure): triangle-split two-pass flash loop.
// smem 69.6 KB -> 3 blocks/SM; uniform stride-68 tiles; every tile a full GEMM.

#define BB 8
#define LL 512
#define DD 64
#define HH 12
#define NROW (BB*LL)
#define NELT (BB*LL*DD)
#define SA 68

typedef unsigned long long u64;

// -------- scratch --------
__device__ float g_P [NELT];          // [z][i][b]
__device__ float g_Pt[BB*DD*LL];      // [z][b][i]
__device__ float g_Tr [2*HH*DD*DD];   // [kc][a][b]
__device__ float g_Trt[2*HH*DD*DD];   // [kc][b][a]
__device__ float g_Gpart[HH*NELT];    // per-c G partials

__device__ __forceinline__ u64 bc2(float v){ u64 r; asm("mov.b64 %0,{%1,%1};":"=l"(r):"f"(v)); return r; }
__device__ __forceinline__ u64 pk2(float lo, float hi){ u64 r; asm("mov.b64 %0,{%1,%2};":"=l"(r):"f"(lo),"f"(hi)); return r; }
__device__ __forceinline__ void f2(u64 &d, u64 a, u64 b){ asm("fma.rn.f32x2 %0,%1,%2,%0;":"+l"(d):"l"(a),"l"(b)); }
__device__ __forceinline__ void m2(u64 &d, u64 s){ asm("mul.rn.f32x2 %0,%0,%1;":"+l"(d):"l"(s)); }
__device__ __forceinline__ float2 up2(u64 v){ float2 f; asm("mov.b64 {%0,%1},%2;":"=f"(f.x),"=f"(f.y):"l"(v)); return f; }
__device__ __forceinline__ unsigned smaddr(const void* p){ return (unsigned)__cvta_generic_to_shared(p); }
__device__ __forceinline__ void cpa16(unsigned s, const void* g){ asm volatile("cp.async.cg.shared.global [%0],[%1],16;"::"r"(s),"l"(g):"memory"); }
__device__ __forceinline__ void cpcommit(){ asm volatile("cp.async.commit_group;":::"memory"); }
__device__ __forceinline__ void cpwait0(){ asm volatile("cp.async.wait_group 0;":::"memory"); }
__device__ __forceinline__ void cpwait1(){ asm volatile("cp.async.wait_group 1;":::"memory"); }

#define STEP4(ACC,P0,P1,P2,P3,B0,B1,B2,B3) do{ \
  f2(ACC[0][0],P0,B0); f2(ACC[0][1],P0,B1); f2(ACC[0][2],P0,B2); f2(ACC[0][3],P0,B3); \
  f2(ACC[1][0],P1,B0); f2(ACC[1][1],P1,B1); f2(ACC[1][2],P1,B2); f2(ACC[1][3],P1,B3); \
  f2(ACC[2][0],P2,B0); f2(ACC[2][1],P2,B1); f2(ACC[2][2],P2,B2); f2(ACC[2][3],P2,B3); \
  f2(ACC[3][0],P3,B0); f2(ACC[3][1],P3,B1); f2(ACC[3][2],P3,B2); f2(ACC[3][3],P3,B3); \
} while(0)

// -------- K0: rearrange ternary --------
__global__ void k_prep_T(const float* __restrict__ ternary) {
    int idx = blockIdx.x * blockDim.x + threadIdx.x;
    if (idx >= 2*DD*DD*HH) return;
    int c = idx % HH; int t = idx / HH;
    int b = t % DD;   t /= DD;
    int a = t % DD;   int k = t / DD;
    float v = 64.0f * ternary[idx];
    int kc = k*HH + c;
    g_Tr [(kc*DD + a)*DD + b] = v;
    g_Trt[(kc*DD + b)*DD + a] = v;
}

// -------- K1: p = softmax_d(q_z)*mask; writes P and P^T --------
__global__ void k_softmax_p(const float* __restrict__ x, const int* __restrict__ mask, int use_g) {
    int gw = (blockIdx.x * blockDim.x + threadIdx.x) >> 5;
    int lane = threadIdx.x & 31;
    if (gw >= NROW) return;
    int base = gw * DD;
    float v0 = x[base + lane], v1 = x[base + lane + 32];
    if (use_g) {
        #pragma unroll
        for (int g = 0; g < HH; g++) {
            v0 += g_Gpart[g*NELT + base + lane];
            v1 += g_Gpart[g*NELT + base + lane + 32];
        }
        v0 *= (1.0f/64.0f); v1 *= (1.0f/64.0f);
    }
    float m = fmaxf(v0, v1);
    #pragma unroll
    for (int off = 16; off; off >>= 1) m = fmaxf(m, __shfl_xor_sync(0xffffffffu, m, off));
    float e0 = __expf(v0 - m), e1 = __expf(v1 - m);
    float s = e0 + e1;
    #pragma unroll
    for (int off = 16; off; off >>= 1) s += __shfl_xor_sync(0xffffffffu, s, off);
    float mm = (mask[gw] != 0) ? 1.0f : 0.0f;
    float inv = mm / s;
    float p0 = e0 * inv, p1 = e1 * inv;
    g_P[base + lane]      = p0;
    g_P[base + lane + 32] = p1;
    int z = gw >> 9, i = gw & 511;
    g_Pt[(z*DD + lane     )*LL + i] = p0;
    g_Pt[(z*DD + lane + 32)*LL + i] = p1;
}

// -------- K2: fused per-(z,c,i0), two triangle passes --------
extern __shared__ float smf[];
__global__ void __launch_bounds__(128, 3) k_fused() {
    float* sA = smf;            // A tile [b][i]      (later: W_U)
    float* R0 = smf + 64*SA;    // T / Pj [b][j] / TrtU
    float* R1 = smf + 2*64*SA;  // Pt / E / TrtL
    float* sV = smf + 3*64*SA;  // V [j][b]           (later: W_L)
    int i0 = blockIdx.x*64, c = blockIdx.y, z = blockIdx.z;
    int it = blockIdx.x;
    int tid = threadIdx.x, tx = tid & 15, ty = tid >> 4;

    float m[8], ss[8];
    #pragma unroll
    for (int r = 0; r < 8; r++) { m[r] = -1e30f; ss[r] = 0.0f; }
    u64 aU[4][4] = {}, aL[4][4] = {};

    #pragma unroll
    for (int pass = 0; pass < 2; pass++) {
        // ---- A prep: A = Pt_tile @ T[pass?HH+c:c]
        const float* Tsrc = &g_Tr[(pass ? HH + c : c)*DD*DD];
        for (int t = tid; t < 1024; t += 128) {
            int r = t >> 4, q = (t & 15) << 2;
            cpa16(smaddr(&R1[r*SA+q]), &g_Pt[(z*DD + r)*LL + i0 + q]);
            cpa16(smaddr(&R0[r*SA+q]), &Tsrc[r*DD + q]);
        }
        cpcommit(); cpwait0(); __syncthreads();
        {
            u64 acc[4][4] = {};
            #pragma unroll 8
            for (int a = 0; a < 64; a++) {
                ulonglong2 p01 = *(const ulonglong2*)&R1[a*SA + ty*8];
                ulonglong2 p23 = *(const ulonglong2*)&R1[a*SA + ty*8 + 4];
                float4 fp = *(const float4*)&R0[a*SA + tx*4];
                u64 b0=bc2(fp.x), b1=bc2(fp.y), b2=bc2(fp.z), b3=bc2(fp.w);
                STEP4(acc, p01.x, p01.y, p23.x, p23.y, b0, b1, b2, b3);
            }
            __syncthreads();     // reads of R0/R1 done; sA overwrite safe
            #pragma unroll
            for (int s = 0; s < 4; s++) {
                float* dst = &sA[(tx*4+s)*SA + ty*8];
                ((ulonglong2*)dst)[0] = make_ulonglong2(acc[0][s], acc[1][s]);
                ((ulonglong2*)dst)[1] = make_ulonglong2(acc[2][s], acc[3][s]);
            }
        }
        __syncthreads();

        int jbeg = pass ? 0 : it;
        int jend = pass ? it : 7;
        for (int t = tid; t < 1024; t += 128) {     // Pj[jbeg] (own group)
            int r = t >> 4, q = (t & 15) << 2;
            cpa16(smaddr(&R0[r*SA+q]), &g_Pt[(z*DD + r)*LL + jbeg*64 + q]);
        }
        cpcommit();
        for (int t = tid; t < 1024; t += 128) {     // V[jbeg] (own group)
            int r = t >> 4, q = (t & 15) << 2;
            cpa16(smaddr(&sV[r*SA+q]), &g_P[(z*LL + jbeg*64 + r)*DD + q]);
        }
        cpcommit();

        u64 (*aT)[4] = pass ? aL : aU;
        #pragma unroll 1
        for (int jt = jbeg; jt <= jend; jt++) {
            cpwait1(); __syncthreads();             // Pj[jt] ready

            // ---- S GEMM
            u64 acc[4][4] = {};
            #pragma unroll 8
            for (int b = 0; b < 64; b++) {
                ulonglong2 a01 = *(const ulonglong2*)&sA[b*SA + ty*8];
                ulonglong2 a23 = *(const ulonglong2*)&sA[b*SA + ty*8 + 4];
                float4 fp = *(const float4*)&R0[b*SA + tx*4];
                u64 b0=bc2(fp.x), b1=bc2(fp.y), b2=bc2(fp.z), b3=bc2(fp.w);
                STEP4(acc, a01.x, a01.y, a23.x, a23.y, b0, b1, b2, b3);
            }
            __syncthreads();                        // done reading R0
            bool pjnext = (jt < jend);
            if (pjnext) {
                for (int t = tid; t < 1024; t += 128) {
                    int r = t >> 4, q = (t & 15) << 2;
                    cpa16(smaddr(&R0[r*SA+q]), &g_Pt[(z*DD + r)*LL + (jt+1)*64 + q]);
                }
                cpcommit();
            }

            // ---- flash update + E write (diag tiles masked per pass)
            bool dg = (jt == it);
            float scv[8];
            #pragma unroll
            for (int rp = 0; rp < 4; rp++) {
                #pragma unroll
                for (int rr = 0; rr < 2; rr++) {
                    int r = rp*2 + rr;
                    int gi = ty*8 + r;
                    float vv[4];
                    #pragma unroll
                    for (int s = 0; s < 4; s++) {
                        float2 f = up2(acc[rp][s]);
                        vv[s] = rr ? f.y : f.x;
                    }
                    if (dg) {
                        #pragma unroll
                        for (int s = 0; s < 4; s++) {
                            int gj = tx*4 + s;
                            if (pass == 0) vv[s] = (gj > gi) ? vv[s] : (gj == gi ? 0.0f : -1e30f);
                            else           vv[s] = (gj < gi) ? vv[s] : -1e30f;
                        }
                    }
                    float tm = fmaxf(fmaxf(vv[0], vv[1]), fmaxf(vv[2], vv[3]));
                    #pragma unroll
                    for (int off = 1; off < 16; off <<= 1)
                        tm = fmaxf(tm, __shfl_xor_sync(0xffffffffu, tm, off));
                    float nm = fmaxf(m[r], tm);
                    float sc = __expf(m[r] - nm);
                    float e0 = __expf(vv[0]-nm), e1 = __expf(vv[1]-nm);
                    float e2 = __expf(vv[2]-nm), e3 = __expf(vv[3]-nm);
                    ss[r] = ss[r]*sc + e0+e1+e2+e3;
                    m[r] = nm; scv[r] = sc;
                    if (dg && pass == 0) {          // j==i in normalizer, not in W
                        if (tx*4+0 == gi) e0 = 0.0f;
                        if (tx*4+1 == gi) e1 = 0.0f;
                        if (tx*4+2 == gi) e2 = 0.0f;
                        if (tx*4+3 == gi) e3 = 0.0f;
                    }
                    int ic = gi ^ ((tx & 3) << 3);  // XOR swizzle
                    R1[(tx*4+0)*SA + ic] = e0;
                    R1[(tx*4+1)*SA + ic] = e1;
                    R1[(tx*4+2)*SA + ic] = e2;
                    R1[(tx*4+3)*SA + ic] = e3;
                }
            }
            // rescale both W accumulators
            #pragma unroll
            for (int rp = 0; rp < 4; rp++) {
                u64 sc2 = pk2(scv[2*rp], scv[2*rp+1]);
                #pragma unroll
                for (int s = 0; s < 4; s++) { m2(aU[rp][s], sc2); m2(aL[rp][s], sc2); }
            }
            if (pjnext) cpwait1(); else cpwait0();  // V[jt] ready
            __syncthreads();                        // E visible + V visible

            // ---- W GEMM: E @ V -> aT
            #pragma unroll 8
            for (int j = 0; j < 64; j++) {
                int base = (ty*8) ^ (((j >> 2) & 3) << 3);
                ulonglong2 p01 = *(const ulonglong2*)&R1[j*SA + base];
                ulonglong2 p23 = *(const ulonglong2*)&R1[j*SA + base + 4];
                float4 fv = *(const float4*)&sV[j*SA + tx*4];
                u64 b0=bc2(fv.x), b1=bc2(fv.y), b2=bc2(fv.z), b3=bc2(fv.w);
                STEP4(aT, p01.x, p01.y, p23.x, p23.y, b0, b1, b2, b3);
            }
            __syncthreads();                        // done reading sV, R1
            if (jt < jend) {
                for (int t = tid; t < 1024; t += 128) {
                    int r = t >> 4, q = (t & 15) << 2;
                    cpa16(smaddr(&sV[r*SA+q]), &g_P[(z*LL + (jt+1)*64 + r)*DD + q]);
                }
                cpcommit();
            }
        }
    }

    // ---- normalize W by 1/sum_exp
    #pragma unroll
    for (int r = 0; r < 8; r++) {
        float sr = ss[r];
        #pragma unroll
        for (int off = 1; off < 16; off <<= 1)
            sr += __shfl_xor_sync(0xffffffffu, sr, off);
        ss[r] = 1.0f / sr;
    }
    #pragma unroll
    for (int rp = 0; rp < 4; rp++) {
        u64 iv2 = pk2(ss[2*rp], ss[2*rp+1]);
        #pragma unroll
        for (int s = 0; s < 4; s++) { m2(aU[rp][s], iv2); m2(aL[rp][s], iv2); }
    }

    // ---- epilogue: G_c = W_U @ Trt[c] + W_L @ Trt[HH+c]
    #pragma unroll
    for (int s = 0; s < 4; s++) {
        float* dU = &sA[(tx*4+s)*SA + ty*8];
        ((ulonglong2*)dU)[0] = make_ulonglong2(aU[0][s], aU[1][s]);
        ((ulonglong2*)dU)[1] = make_ulonglong2(aU[2][s], aU[3][s]);
        float* dL = &sV[(tx*4+s)*SA + ty*8];
        ((ulonglong2*)dL)[0] = make_ulonglong2(aL[0][s], aL[1][s]);
        ((ulonglong2*)dL)[1] = make_ulonglong2(aL[2][s], aL[3][s]);
    }
    for (int t = tid; t < 1024; t += 128) {
        int r = t >> 4, q = (t & 15) << 2;
        *(float4*)&R0[r*SA+q] = *(const float4*)&g_Trt[((c   )*DD + r)*DD + q];
        *(float4*)&R1[r*SA+q] = *(const float4*)&g_Trt[((HH+c)*DD + r)*DD + q];
    }
    __syncthreads();
    u64 acc[4][4] = {};
    #pragma unroll 4
    for (int b = 0; b < 64; b++) {
        ulonglong2 w01 = *(const ulonglong2*)&sA[b*SA + ty*8];
        ulonglong2 w23 = *(const ulonglong2*)&sA[b*SA + ty*8 + 4];
        float4 ft = *(const float4*)&R0[b*SA + tx*4];
        u64 b0=bc2(ft.x), b1=bc2(ft.y), b2=bc2(ft.z), b3=bc2(ft.w);
        STEP4(acc, w01.x, w01.y, w23.x, w23.y, b0, b1, b2, b3);
        ulonglong2 y01 = *(const ulonglong2*)&sV[b*SA + ty*8];
        ulonglong2 y23 = *(const ulonglong2*)&sV[b*SA + ty*8 + 4];
        float4 fl = *(const float4*)&R1[b*SA + tx*4];
        u64 c0=bc2(fl.x), c1=bc2(fl.y), c2=bc2(fl.z), c3=bc2(fl.w);
        STEP4(acc, y01.x, y01.y, y23.x, y23.y, c0, c1, c2, c3);
    }
    #pragma unroll
    for (int rp = 0; rp < 4; rp++) {
        float2 x0 = up2(acc[rp][0]), x1 = up2(acc[rp][1]);
        float2 x2 = up2(acc[rp][2]), x3 = up2(acc[rp][3]);
        int i = i0 + ty*8 + rp*2;
        *(float4*)&g_Gpart[(c*NROW + z*LL + i    )*DD + tx*4] = make_float4(x0.x, x1.x, x2.x, x3.x);
        *(float4*)&g_Gpart[(c*NROW + z*LL + i + 1)*DD + tx*4] = make_float4(x0.y, x1.y, x2.y, x3.y);
    }
}

// -------- K3: out = (x + sum Gpart) / 64 --------
__global__ void k_final(const float* __restrict__ x, float* __restrict__ out) {
    int idx = blockIdx.x * blockDim.x + threadIdx.x;
    if (idx >= NELT) return;
    float v = x[idx];
    #pragma unroll
    for (int g = 0; g < HH; g++) v += g_Gpart[g*NELT + idx];
    out[idx] = v * (1.0f/64.0f);
}

extern "C" void kernel_launch(void* const* d_in, const int* in_sizes, int n_in,
                              void* d_out, int out_size) {
    const float* x       = (const float*)d_in[0];
    const int*   mask    = (const int*)d_in[1];
    const float* ternary = (const float*)d_in[2];
    for (int i = 0; i < n_in; i++) {
        if      (in_sizes[i] == NELT)        x       = (const float*)d_in[i];
        else if (in_sizes[i] == BB*LL)       mask    = (const int*)d_in[i];
        else if (in_sizes[i] == 2*DD*DD*HH)  ternary = (const float*)d_in[i];
    }
    const int SMEM_F = 4*64*SA*4;   // 69632 B -> 3 blocks/SM
    cudaFuncSetAttribute(k_fused, cudaFuncAttributeMaxDynamicSharedMemorySize, SMEM_F);

    k_prep_T<<<96, 1024>>>(ternary);
    for (int it = 0; it < 4; it++) {
        k_softmax_p<<<NROW/4, 128>>>(x, mask, it > 0 ? 1 : 0);
        k_fused<<<dim3(8, HH, BB), 128, SMEM_F>>>();
    }
    k_final<<<(NELT + 255)/256, 256>>>(x, (float*)d_out);
}